// round 15
// baseline (speedup 1.0000x reference)
#include <cuda_runtime.h>
#include <cuda_bf16.h>
#include <cuda_fp16.h>
#include <math.h>
#include <stdint.h>

#define BB 2
#define NN 4096
#define LL 512
#define CC 2048
#define HH 16
#define DD 128
#define MTOK (BB*NN)
#define MKV  (BB*LL)
#define L2E  1.4426950408889634f
#define QFOLD (0.08838834764831845f * 1.4426950408889634f)  // inv_sqrt(128)*log2e

// -------------------- scratch ---------------------------------------------
__device__ int8_t g_qwq[(size_t)CC*CC];
__device__ float  g_swq[CC];
__device__ int8_t g_qwo[(size_t)CC*CC];
__device__ float  g_swo[CC];
__device__ int8_t g_qx[(size_t)MTOK*CC];
__device__ float  g_sx[MTOK];
__device__ float  g_o[(size_t)MTOK*CC];
__device__ int8_t g_qo[(size_t)MTOK*CC];
__device__ float  g_so[MTOK];
// fp16 hi/lo split planes
__device__ __half g_qh_[(size_t)MTOK*CC];
__device__ __half g_ql_[(size_t)MTOK*CC];
__device__ __half g_kh_[(size_t)MKV*CC];
__device__ __half g_kl_[(size_t)MKV*CC];
__device__ __half g_vh_[(size_t)MKV*CC];
__device__ __half g_vl_[(size_t)MKV*CC];
__device__ __half g_ch_[(size_t)MKV*CC];     // cond split
__device__ __half g_cl_[(size_t)MKV*CC];
__device__ __half g_wkh_[(size_t)CC*CC];
__device__ __half g_wkl_[(size_t)CC*CC];
__device__ __half g_wvh_[(size_t)CC*CC];
__device__ __half g_wvl_[(size_t)CC*CC];

// -------------------- helpers ---------------------------------------------
__device__ __forceinline__ uint32_t smem_u32(const void* p) {
    uint32_t a;
    asm("{ .reg .u64 t; cvta.to.shared.u64 t, %1; cvt.u32.u64 %0, t; }"
        : "=r"(a) : "l"(p));
    return a;
}
__device__ __forceinline__ void cp16(uint32_t dst, const void* src) {
    asm volatile("cp.async.cg.shared.global [%0], [%1], 16;" :: "r"(dst), "l"(src));
}
#define SW128(x) ((x) ^ (((x) >> 3) & 0x70))

#define LDSM4(r0, r1, r2, r3, addr) \
    asm volatile("ldmatrix.sync.aligned.m8n8.x4.shared.b16 {%0,%1,%2,%3}, [%4];" \
                 : "=r"(r0), "=r"(r1), "=r"(r2), "=r"(r3) : "r"(addr))
#define LDSM4T(r0, r1, r2, r3, addr) \
    asm volatile("ldmatrix.sync.aligned.m8n8.x4.trans.shared.b16 {%0,%1,%2,%3}, [%4];" \
                 : "=r"(r0), "=r"(r1), "=r"(r2), "=r"(r3) : "r"(addr))

// int8 IMMA: m16n8k32, s32 accumulate. Fragment layout is byte-identical to
// the b16 m16n8k16 layout (one b16 = two consecutive s8 k-elements), so the
// same ldmatrix addressing and register pairing apply.
__device__ __forceinline__ void mma_i8(int* d,
    uint32_t a0, uint32_t a1, uint32_t a2, uint32_t a3, uint32_t b0, uint32_t b1)
{
    asm volatile(
        "mma.sync.aligned.m16n8k32.row.col.s32.s8.s8.s32 "
        "{%0,%1,%2,%3}, {%4,%5,%6,%7}, {%8,%9}, {%0,%1,%2,%3};"
        : "+r"(d[0]), "+r"(d[1]), "+r"(d[2]), "+r"(d[3])
        : "r"(a0), "r"(a1), "r"(a2), "r"(a3), "r"(b0), "r"(b1));
}
__device__ __forceinline__ void mma_h(float* d, const uint32_t* a,
                                      uint32_t b0, uint32_t b1)
{
    asm volatile(
        "mma.sync.aligned.m16n8k16.row.col.f32.f16.f16.f32 "
        "{%0,%1,%2,%3}, {%4,%5,%6,%7}, {%8,%9}, {%0,%1,%2,%3};"
        : "+f"(d[0]), "+f"(d[1]), "+f"(d[2]), "+f"(d[3])
        : "r"(a[0]), "r"(a[1]), "r"(a[2]), "r"(a[3]), "r"(b0), "r"(b1));
}

__device__ __forceinline__ float exp2_poly(float t) {
    t = fmaxf(t, -126.f);
    float fi = rintf(t);
    float f = t - fi;
    float p = 1.5403530e-4f;
    p = fmaf(p, f, 1.3333558e-3f);
    p = fmaf(p, f, 9.6181292e-3f);
    p = fmaf(p, f, 5.5504109e-2f);
    p = fmaf(p, f, 2.4022651e-1f);
    p = fmaf(p, f, 6.9314718e-1f);
    p = fmaf(p, f, 1.0f);
    return __uint_as_float(__float_as_uint(p) + ((int)fi << 23));
}
__device__ __forceinline__ uint32_t packh(float x, float y) {
    __half2 h = __halves2half2(__float2half_rn(x), __float2half_rn(y));
    return *(uint32_t*)&h;
}
__device__ __forceinline__ void split2(float x, float y, uint32_t& hi, uint32_t& lo) {
    __half hx = __float2half_rn(x), hy = __float2half_rn(y);
    __half lx = __float2half_rn(x - __half2float(hx));
    __half ly = __float2half_rn(y - __half2float(hy));
    __half2 h = __halves2half2(hx, hy);
    __half2 l = __halves2half2(lx, ly);
    hi = *(uint32_t*)&h;
    lo = *(uint32_t*)&l;
}

// -------------------- quant (int8 output) ----------------------------------
__global__ void quant_rows(const float* __restrict__ src,
                           int8_t* __restrict__ qdst,
                           float* __restrict__ sdst, int K) {
    int row = blockIdx.x;
    const float* p = src + (size_t)row * K;
    float m = 0.f;
    for (int i = threadIdx.x; i < K; i += blockDim.x) m = fmaxf(m, fabsf(p[i]));
    __shared__ float red[256];
    red[threadIdx.x] = m;
    __syncthreads();
    for (int s = 128; s > 0; s >>= 1) {
        if (threadIdx.x < s) red[threadIdx.x] = fmaxf(red[threadIdx.x], red[threadIdx.x + s]);
        __syncthreads();
    }
    float sc = fmaxf(red[0] / 127.0f, 1e-8f);
    int8_t* q = qdst + (size_t)row * K;
    for (int i = threadIdx.x; i < K; i += blockDim.x) {
        float r = rintf(p[i] / sc);
        r = fminf(fmaxf(r, -127.f), 127.f);
        q[i] = (int8_t)r;
    }
    if (threadIdx.x == 0) sdst[row] = sc;
}

// -------------------- fp32 -> fp16 hi/lo split -----------------------------
__global__ void split_f32(const float* __restrict__ src, __half* __restrict__ h,
                          __half* __restrict__ l, int n) {
    int i = blockIdx.x * blockDim.x + threadIdx.x;
    if (i < n) {
        float x = src[i];
        __half hx = __float2half_rn(x);
        h[i] = hx;
        l[i] = __float2half_rn(x - __half2float(hx));
    }
}

// -------------------- int8 IMMA W8A8 GEMM, CTA tile 128x256 ----------------
// out[m][n] = float( sum_k qa[m][k]*qw[n][k] ) * (sa[m]*sw[n]) + bias[n]
// s32 accumulation: exact. K-chunk = 128 int8 (128B rows, SW128).
// 8 warps 2(m) x 4(n); warp tile 64x64; per kt (k32): 8 LDSM, 32 IMMA.
#define GNST 3
#define GSTA 16384u                       // A plane: 128 rows x 128B
#define GSTB 32768u                       // B plane: 256 rows x 128B
#define GSTAGE_BYTES (GSTA + GSTB)        // 48KB
#define GSM_A(s) ((unsigned)(s) * GSTAGE_BYTES)
#define GSM_B(s) (GSM_A(s) + GSTA)
#define GEMM_SMEM (GNST * GSTAGE_BYTES)   // 144KB
#define GNCH (CC / 128)                   // 16 K-chunks of 128 int8

__device__ __forceinline__ void gemm_load_stage(
    uint32_t smem_base, int s, int ks, int m0, int n0, int tid,
    const int8_t* __restrict__ A, const int8_t* __restrict__ W)
{
    size_t coff = (size_t)ks * 128;        // byte offset into the K dim
    uint32_t abase = smem_base + GSM_A(s);
    uint32_t bbase = smem_base + GSM_B(s);
#pragma unroll
    for (int j = 0; j < 4; j++) {          // A: 128 rows x 8 granules
        int g = tid + j * 256, r = g >> 3, i = g & 7;
        cp16(abase + SW128((uint32_t)(r * 128 + i * 16)),
             (const char*)(A + (size_t)(m0 + r) * CC + coff) + i * 16);
    }
#pragma unroll
    for (int j = 0; j < 8; j++) {          // B: 256 rows x 8 granules
        int g = tid + j * 256, r = g >> 3, i = g & 7;
        cp16(bbase + SW128((uint32_t)(r * 128 + i * 16)),
             (const char*)(W + (size_t)(n0 + r) * CC + coff) + i * 16);
    }
    asm volatile("cp.async.commit_group;" ::: "memory");
}

__global__ __launch_bounds__(256, 1) void gemm_tc(
    const int8_t* __restrict__ A, const int8_t* __restrict__ W,
    const float* __restrict__ sa, const float* __restrict__ sw,
    const float* __restrict__ bias, float* __restrict__ out,
    __half* __restrict__ outh, __half* __restrict__ outl, float fold)
{
    extern __shared__ char smem[];
    uint32_t sb = smem_u32(smem);
    int tid = threadIdx.x;
    int wid = tid >> 5, lid = tid & 31;
    int m0 = blockIdx.y * 128, n0 = blockIdx.x * 256;
    int wm = wid >> 2, wn = wid & 3;
    int lrow = (lid & 7) + ((lid >> 3) & 1) * 8;
    int lcol = (lid >> 4) * 16;

    int acc[4][8][4];
#pragma unroll
    for (int mt = 0; mt < 4; mt++)
#pragma unroll
        for (int nt = 0; nt < 8; nt++)
#pragma unroll
            for (int q = 0; q < 4; q++) acc[mt][nt][q] = 0;

    gemm_load_stage(sb, 0, 0, m0, n0, tid, A, W);
    gemm_load_stage(sb, 1, 1, m0, n0, tid, A, W);
    gemm_load_stage(sb, 2, 2, m0, n0, tid, A, W);

    int a_row = wm * 64 + lrow;
    int b_row = wn * 64 + lrow;

    for (int ks = 0; ks < GNCH; ks++) {
        int s = ks % GNST;
        if (ks < GNCH - 2)       asm volatile("cp.async.wait_group 2;" ::: "memory");
        else if (ks == GNCH - 2) asm volatile("cp.async.wait_group 1;" ::: "memory");
        else                     asm volatile("cp.async.wait_group 0;" ::: "memory");
        __syncthreads();
        uint32_t abase = sb + GSM_A(s);
        uint32_t bbase = sb + GSM_B(s);
#pragma unroll
        for (int kt = 0; kt < 4; kt++) {   // 4 x k32 per 128-byte chunk
            int kb = kt * 32 + lcol;
            uint32_t af[4][4];
#pragma unroll
            for (int mt = 0; mt < 4; mt++)
                LDSM4(af[mt][0], af[mt][1], af[mt][2], af[mt][3],
                      abase + SW128((uint32_t)((a_row + mt * 16) * 128 + kb)));
            uint32_t bf[4][4];
#pragma unroll
            for (int np = 0; np < 4; np++)
                LDSM4(bf[np][0], bf[np][1], bf[np][2], bf[np][3],
                      bbase + SW128((uint32_t)((b_row + np * 16) * 128 + kb)));
#pragma unroll
            for (int mt = 0; mt < 4; mt++)
#pragma unroll
                for (int np = 0; np < 4; np++) {
                    mma_i8(acc[mt][np * 2 + 0], af[mt][0], af[mt][1], af[mt][2], af[mt][3],
                           bf[np][0], bf[np][2]);
                    mma_i8(acc[mt][np * 2 + 1], af[mt][0], af[mt][1], af[mt][2], af[mt][3],
                           bf[np][1], bf[np][3]);
                }
        }
        __syncthreads();
        if (ks + GNST < GNCH)
            gemm_load_stage(sb, s, ks + GNST, m0, n0, tid, A, W);
    }

    int g = lid >> 2, t = lid & 3;
#pragma unroll
    for (int mt = 0; mt < 4; mt++) {
        int mA = m0 + wm * 64 + mt * 16 + g;
        int mB = mA + 8;
        float saA = sa[mA], saB = sa[mB];
#pragma unroll
        for (int nt = 0; nt < 8; nt++) {
            int n = n0 + wn * 64 + (nt >> 1) * 16 + (nt & 1) * 8 + t * 2;
            float2 vsw = *(const float2*)(sw + n);
            float2 vbi = *(const float2*)(bias + n);
            float yA0 = (float)acc[mt][nt][0] * (saA * vsw.x) + vbi.x;
            float yA1 = (float)acc[mt][nt][1] * (saA * vsw.y) + vbi.y;
            float yB0 = (float)acc[mt][nt][2] * (saB * vsw.x) + vbi.x;
            float yB1 = (float)acc[mt][nt][3] * (saB * vsw.y) + vbi.y;
            if (outh) {
                uint32_t hA, lA, hB, lB;
                split2(yA0 * fold, yA1 * fold, hA, lA);
                split2(yB0 * fold, yB1 * fold, hB, lB);
                *(uint32_t*)(outh + (size_t)mA * CC + n) = hA;
                *(uint32_t*)(outl + (size_t)mA * CC + n) = lA;
                *(uint32_t*)(outh + (size_t)mB * CC + n) = hB;
                *(uint32_t*)(outl + (size_t)mB * CC + n) = lB;
            } else {
                *(float2*)(out + (size_t)mA * CC + n) = make_float2(yA0, yA1);
                *(float2*)(out + (size_t)mB * CC + n) = make_float2(yB0, yB1);
            }
        }
    }
}

// -------------------- fp16-split tensor GEMM for K/V projections -----------
#define KVPL 16384u
#define KVSTAGE (4u * KVPL)             // Ah Al Bh Bl = 64KB
#define KV_SMEM (2u * KVSTAGE)          // 128KB, 2 stages
#define KVNCH (CC / 64)

__device__ __forceinline__ void kv_load_stage(
    uint32_t sbase, int s, int ks, int m0, int n0, int tid,
    const __half* __restrict__ Bh, const __half* __restrict__ Bl)
{
    size_t coff = (size_t)ks * 64;
    uint32_t st = sbase + (uint32_t)s * KVSTAGE;
#pragma unroll
    for (int j = 0; j < 16; j++) {
        int gi = tid + j * 256;
        int plane = gi >> 10;            // 0:Ah 1:Al 2:Bh 3:Bl
        int within = gi & 1023;
        int r = within >> 3, i = within & 7;
        const __half* arr = (plane == 0) ? g_ch_ : (plane == 1) ? g_cl_
                          : (plane == 2) ? Bh : Bl;
        int row = (plane < 2 ? m0 : n0) + r;
        cp16(st + (uint32_t)plane * KVPL + SW128((uint32_t)(r * 128 + i * 16)),
             arr + (size_t)row * CC + coff + i * 8);
    }
    asm volatile("cp.async.commit_group;" ::: "memory");
}

__global__ __launch_bounds__(256, 1) void gemm_kv_tc(
    const float* __restrict__ bk, const float* __restrict__ bv)
{
    extern __shared__ char smem[];
    uint32_t sb = smem_u32(smem);
    int tid = threadIdx.x;
    int wid = tid >> 5, lid = tid & 31;
    int m0 = blockIdx.y * 128, n0 = blockIdx.x * 128;
    int wm = wid >> 2, wn = wid & 3;
    int z = blockIdx.z;
    const __half* Bh = z ? g_wvh_ : g_wkh_;
    const __half* Bl = z ? g_wvl_ : g_wkl_;
    const float* bias = z ? bv : bk;
    __half* outh = z ? g_vh_ : g_kh_;
    __half* outl = z ? g_vl_ : g_kl_;

    int lrow = (lid & 7) + ((lid >> 3) & 1) * 8;
    int lcol = (lid >> 4) * 16;

    float acc[4][4][4];
#pragma unroll
    for (int mt = 0; mt < 4; mt++)
#pragma unroll
        for (int nt = 0; nt < 4; nt++)
#pragma unroll
            for (int q = 0; q < 4; q++) acc[mt][nt][q] = 0.f;

    kv_load_stage(sb, 0, 0, m0, n0, tid, Bh, Bl);
    kv_load_stage(sb, 1, 1, m0, n0, tid, Bh, Bl);

    int a_row = wm * 64 + lrow;
    int b_row = wn * 32 + lrow;

    for (int ks = 0; ks < KVNCH; ks++) {
        int s = ks & 1;
        if (ks < KVNCH - 1) asm volatile("cp.async.wait_group 1;" ::: "memory");
        else                asm volatile("cp.async.wait_group 0;" ::: "memory");
        __syncthreads();
        uint32_t st = sb + (uint32_t)s * KVSTAGE;
#pragma unroll
        for (int kt = 0; kt < 4; kt++) {
            int kb = kt * 32 + lcol;
            uint32_t ah[4][4], al_[4][4];
#pragma unroll
            for (int mt = 0; mt < 4; mt++) {
                uint32_t ro = SW128((uint32_t)((a_row + mt * 16) * 128 + kb));
                LDSM4(ah[mt][0], ah[mt][1], ah[mt][2], ah[mt][3], st + ro);
                LDSM4(al_[mt][0], al_[mt][1], al_[mt][2], al_[mt][3], st + KVPL + ro);
            }
            uint32_t bh[2][4], bl_[2][4];
#pragma unroll
            for (int np = 0; np < 2; np++) {
                uint32_t ro = SW128((uint32_t)((b_row + np * 16) * 128 + kb));
                LDSM4(bh[np][0], bh[np][1], bh[np][2], bh[np][3], st + 2u * KVPL + ro);
                LDSM4(bl_[np][0], bl_[np][1], bl_[np][2], bl_[np][3], st + 3u * KVPL + ro);
            }
#pragma unroll
            for (int mt = 0; mt < 4; mt++)
#pragma unroll
                for (int np = 0; np < 2; np++) {
                    mma_h(acc[mt][np * 2 + 0], ah[mt],  bh[np][0],  bh[np][2]);
                    mma_h(acc[mt][np * 2 + 0], ah[mt],  bl_[np][0], bl_[np][2]);
                    mma_h(acc[mt][np * 2 + 0], al_[mt], bh[np][0],  bh[np][2]);
                    mma_h(acc[mt][np * 2 + 1], ah[mt],  bh[np][1],  bh[np][3]);
                    mma_h(acc[mt][np * 2 + 1], ah[mt],  bl_[np][1], bl_[np][3]);
                    mma_h(acc[mt][np * 2 + 1], al_[mt], bh[np][1],  bh[np][3]);
                }
        }
        __syncthreads();
        if (ks + 2 < KVNCH)
            kv_load_stage(sb, s, ks + 2, m0, n0, tid, Bh, Bl);
    }

    int g = lid >> 2, t = lid & 3;
#pragma unroll
    for (int mt = 0; mt < 4; mt++) {
        int mA = m0 + wm * 64 + mt * 16 + g;
        int mB = mA + 8;
#pragma unroll
        for (int nt = 0; nt < 4; nt++) {
            int n = n0 + wn * 32 + nt * 8 + t * 2;
            float2 vbi = *(const float2*)(bias + n);
            uint32_t hA, lA, hB, lB;
            split2(acc[mt][nt][0] + vbi.x, acc[mt][nt][1] + vbi.y, hA, lA);
            split2(acc[mt][nt][2] + vbi.x, acc[mt][nt][3] + vbi.y, hB, lB);
            *(uint32_t*)(outh + (size_t)mA * CC + n) = hA;
            *(uint32_t*)(outl + (size_t)mA * CC + n) = lA;
            *(uint32_t*)(outh + (size_t)mB * CC + n) = hB;
            *(uint32_t*)(outl + (size_t)mB * CC + n) = lB;
        }
    }
}

// -------------------- fp16-split tensor-core flash attention ---------------
#define ATT_SMEM (192*1024)

__device__ __forceinline__ void attn_load_kv(uint32_t base, int chunk,
                                             int b, int h, int tid) {
    size_t rowbase = (size_t)b * LL + chunk * 64;
#pragma unroll
    for (int j = 0; j < 16; j++) {
        int gi = tid + j * 256;
        int plane = gi >> 9;
        int within = gi & 511;
        int r = within >> 3, i = within & 7;
        const __half* arr = (plane < 2) ? g_kh_ : (plane < 4) ? g_kl_
                          : (plane < 6) ? g_vh_ : g_vl_;
        cp16(base + (uint32_t)plane * 8192u + SW128((uint32_t)(r * 128 + i * 16)),
             arr + (rowbase + r) * CC + h * DD + (plane & 1) * 64 + i * 8);
    }
    asm volatile("cp.async.commit_group;" ::: "memory");
}

__global__ __launch_bounds__(256, 1) void attn_tc(const float* __restrict__ mask)
{
    extern __shared__ char smem[];
    uint32_t sb = smem_u32(smem);
    int tid = threadIdx.x;
    int wid = tid >> 5, lid = tid & 31;
    int b = blockIdx.y >> 4, h = blockIdx.y & 15;
    int n0 = blockIdx.x * 128;
    int lrow = (lid & 7) + ((lid >> 3) & 1) * 8;
    int lcol = (lid >> 4) * 16;
    int g = lid >> 2, t = lid & 3;

    {
        size_t rowbase = (size_t)b * NN + n0;
#pragma unroll
        for (int j = 0; j < 16; j++) {
            int gi = tid + j * 256;
            int plane = gi >> 10;
            int within = gi & 1023;
            int r = within >> 3, i = within & 7;
            const __half* arr = (plane < 2) ? g_qh_ : g_ql_;
            cp16(sb + (uint32_t)plane * 16384u + SW128((uint32_t)(r * 128 + i * 16)),
                 arr + (rowbase + r) * CC + h * DD + (plane & 1) * 64 + i * 8);
        }
        asm volatile("cp.async.commit_group;" ::: "memory");
    }
    attn_load_kv(sb + 65536u, 0, b, h, tid);

    asm volatile("cp.async.wait_group 1;" ::: "memory");
    __syncthreads();
    uint32_t qh_f[8][4], ql_f[8][4];
#pragma unroll
    for (int kt = 0; kt < 8; kt++) {
        uint32_t ro = SW128((uint32_t)((wid * 16 + lrow) * 128 + (kt & 3) * 32 + lcol));
        uint32_t ph = (uint32_t)(kt >> 2) * 16384u;
        LDSM4(qh_f[kt][0], qh_f[kt][1], qh_f[kt][2], qh_f[kt][3], sb + ph + ro);
        LDSM4(ql_f[kt][0], ql_f[kt][1], ql_f[kt][2], ql_f[kt][3], sb + 32768u + ph + ro);
    }
    __syncthreads();
    attn_load_kv(sb, 1, b, h, tid);

    float m0r = -INFINITY, m1r = -INFINITY, l0r = 0.f, l1r = 0.f;
    float oacc[16][4];
#pragma unroll
    for (int j = 0; j < 16; j++)
#pragma unroll
        for (int q = 0; q < 4; q++) oacc[j][q] = 0.f;

    const float* mr0 = mask + ((size_t)b * NN + n0 + wid * 16 + g) * LL + 2 * t;
    const float* mr1 = mr0 + 8 * LL;

    for (int c = 0; c < LL / 64; c++) {
        uint32_t kvb = (c & 1) ? sb : (sb + 65536u);
        if (c < LL / 64 - 1) asm volatile("cp.async.wait_group 1;" ::: "memory");
        else                 asm volatile("cp.async.wait_group 0;" ::: "memory");
        __syncthreads();

        float sacc[8][4];
#pragma unroll
        for (int j = 0; j < 8; j++) {
            float2 a = *(const float2*)(mr0 + c * 64 + j * 8);
            float2 d = *(const float2*)(mr1 + c * 64 + j * 8);
            sacc[j][0] = a.x * L2E; sacc[j][1] = a.y * L2E;
            sacc[j][2] = d.x * L2E; sacc[j][3] = d.y * L2E;
        }
#pragma unroll
        for (int kt = 0; kt < 8; kt++) {
            uint32_t pk = (uint32_t)(kt >> 2) * 8192u;
            uint32_t kb = (uint32_t)((kt & 3) * 32 + lcol);
#pragma unroll
            for (int j16 = 0; j16 < 4; j16++) {
                uint32_t ro = SW128((uint32_t)((j16 * 16 + lrow) * 128) + kb);
                uint32_t kh0, kh1, kh2, kh3, kl0, kl1, kl2, kl3;
                LDSM4(kh0, kh1, kh2, kh3, kvb + pk + ro);
                LDSM4(kl0, kl1, kl2, kl3, kvb + 16384u + pk + ro);
                mma_h(sacc[2 * j16],     qh_f[kt], kh0, kh2);
                mma_h(sacc[2 * j16],     qh_f[kt], kl0, kl2);
                mma_h(sacc[2 * j16],     ql_f[kt], kh0, kh2);
                mma_h(sacc[2 * j16 + 1], qh_f[kt], kh1, kh3);
                mma_h(sacc[2 * j16 + 1], qh_f[kt], kl1, kl3);
                mma_h(sacc[2 * j16 + 1], ql_f[kt], kh1, kh3);
            }
        }

        float mx0 = -INFINITY, mx1 = -INFINITY;
#pragma unroll
        for (int j = 0; j < 8; j++) {
            mx0 = fmaxf(mx0, fmaxf(sacc[j][0], sacc[j][1]));
            mx1 = fmaxf(mx1, fmaxf(sacc[j][2], sacc[j][3]));
        }
#pragma unroll
        for (int off = 1; off < 4; off <<= 1) {
            mx0 = fmaxf(mx0, __shfl_xor_sync(0xffffffffu, mx0, off));
            mx1 = fmaxf(mx1, __shfl_xor_sync(0xffffffffu, mx1, off));
        }
        float nm0 = fmaxf(m0r, mx0), nm1 = fmaxf(m1r, mx1);
        float cr0 = exp2_poly(m0r - nm0), cr1 = exp2_poly(m1r - nm1);
        m0r = nm0; m1r = nm1;

        uint32_t pa_h[4][4], pa_l[4][4];
        float rs0 = 0.f, rs1 = 0.f;
#pragma unroll
        for (int j = 0; j < 8; j++) {
            float p0 = exp2_poly(sacc[j][0] - nm0);
            float p1 = exp2_poly(sacc[j][1] - nm0);
            float p2 = exp2_poly(sacc[j][2] - nm1);
            float p3 = exp2_poly(sacc[j][3] - nm1);
            rs0 += p0 + p1; rs1 += p2 + p3;
            uint32_t h01 = packh(p0, p1), h23 = packh(p2, p3);
            __half2 hh01 = *(__half2*)&h01, hh23 = *(__half2*)&h23;
            uint32_t l01 = packh(p0 - __low2float(hh01),  p1 - __high2float(hh01));
            uint32_t l23 = packh(p2 - __low2float(hh23),  p3 - __high2float(hh23));
            int kt2 = j >> 1, sl = (j & 1) * 2;
            pa_h[kt2][sl] = h01; pa_h[kt2][sl + 1] = h23;
            pa_l[kt2][sl] = l01; pa_l[kt2][sl + 1] = l23;
        }
#pragma unroll
        for (int off = 1; off < 4; off <<= 1) {
            rs0 += __shfl_xor_sync(0xffffffffu, rs0, off);
            rs1 += __shfl_xor_sync(0xffffffffu, rs1, off);
        }
        l0r = l0r * cr0 + rs0;
        l1r = l1r * cr1 + rs1;
#pragma unroll
        for (int j = 0; j < 16; j++) {
            oacc[j][0] *= cr0; oacc[j][1] *= cr0;
            oacc[j][2] *= cr1; oacc[j][3] *= cr1;
        }

#pragma unroll
        for (int lt = 0; lt < 4; lt++) {
#pragma unroll
            for (int dq = 0; dq < 8; dq++) {
                uint32_t pv = (uint32_t)(4 + (dq >> 2)) * 8192u;
                uint32_t ro = SW128((uint32_t)((lt * 16 + lrow) * 128 + (dq & 3) * 32 + lcol));
                uint32_t vh0, vh1, vh2, vh3, vl0, vl1, vl2, vl3;
                LDSM4T(vh0, vh1, vh2, vh3, kvb + pv + ro);
                LDSM4T(vl0, vl1, vl2, vl3, kvb + 16384u + pv + ro);
                mma_h(oacc[2 * dq],     pa_h[lt], vh0, vh1);
                mma_h(oacc[2 * dq],     pa_h[lt], vl0, vl1);
                mma_h(oacc[2 * dq],     pa_l[lt], vh0, vh1);
                mma_h(oacc[2 * dq + 1], pa_h[lt], vh2, vh3);
                mma_h(oacc[2 * dq + 1], pa_h[lt], vl2, vl3);
                mma_h(oacc[2 * dq + 1], pa_l[lt], vh2, vh3);
            }
        }
        __syncthreads();
        if (c + 2 < LL / 64)
            attn_load_kv(kvb, c + 2, b, h, tid);
    }

    float inv0 = 1.f / l0r, inv1 = 1.f / l1r;
    float* o0 = g_o + ((size_t)b * NN + n0 + wid * 16 + g) * CC + h * DD + 2 * t;
    float* o1 = o0 + 8 * (size_t)CC;
#pragma unroll
    for (int dn = 0; dn < 16; dn++) {
        *(float2*)(o0 + dn * 8) = make_float2(oacc[dn][0] * inv0, oacc[dn][1] * inv0);
        *(float2*)(o1 + dn * 8) = make_float2(oacc[dn][2] * inv1, oacc[dn][3] * inv1);
    }
}

// -------------------- launcher --------------------------------------------
extern "C" void kernel_launch(void* const* d_in, const int* in_sizes, int n_in,
                              void* d_out, int out_size) {
    const float* x    = (const float*)d_in[0];
    const float* cond = (const float*)d_in[1];
    const float* mask = (const float*)d_in[2];
    const float* wq   = (const float*)d_in[3];
    const float* bq   = (const float*)d_in[4];
    const float* wk   = (const float*)d_in[5];
    const float* bk   = (const float*)d_in[6];
    const float* wv   = (const float*)d_in[7];
    const float* bv   = (const float*)d_in[8];
    const float* wo   = (const float*)d_in[9];
    const float* bo   = (const float*)d_in[10];
    float* out = (float*)d_out;

    void *p_qwq, *p_swq, *p_qwo, *p_swo, *p_qx, *p_sx, *p_o, *p_qo, *p_so;
    void *p_qh, *p_ql, *p_ch, *p_cl, *p_wkh, *p_wkl, *p_wvh, *p_wvl;
    cudaGetSymbolAddress(&p_qwq, g_qwq);
    cudaGetSymbolAddress(&p_swq, g_swq);
    cudaGetSymbolAddress(&p_qwo, g_qwo);
    cudaGetSymbolAddress(&p_swo, g_swo);
    cudaGetSymbolAddress(&p_qx,  g_qx);
    cudaGetSymbolAddress(&p_sx,  g_sx);
    cudaGetSymbolAddress(&p_o,   g_o);
    cudaGetSymbolAddress(&p_qo,  g_qo);
    cudaGetSymbolAddress(&p_so,  g_so);
    cudaGetSymbolAddress(&p_qh,  g_qh_);
    cudaGetSymbolAddress(&p_ql,  g_ql_);
    cudaGetSymbolAddress(&p_ch,  g_ch_);
    cudaGetSymbolAddress(&p_cl,  g_cl_);
    cudaGetSymbolAddress(&p_wkh, g_wkh_);
    cudaGetSymbolAddress(&p_wkl, g_wkl_);
    cudaGetSymbolAddress(&p_wvh, g_wvh_);
    cudaGetSymbolAddress(&p_wvl, g_wvl_);

    cudaFuncSetAttribute(gemm_tc,
                         cudaFuncAttributeMaxDynamicSharedMemorySize, GEMM_SMEM);
    cudaFuncSetAttribute(gemm_kv_tc,
                         cudaFuncAttributeMaxDynamicSharedMemorySize, KV_SMEM);
    cudaFuncSetAttribute(attn_tc,
                         cudaFuncAttributeMaxDynamicSharedMemorySize, ATT_SMEM);

    // 1. quantize weights + activations (int8); split cond and K/V weights
    quant_rows<<<CC, 256>>>(wq, (int8_t*)p_qwq, (float*)p_swq, CC);
    quant_rows<<<CC, 256>>>(wo, (int8_t*)p_qwo, (float*)p_swo, CC);
    quant_rows<<<MTOK, 256>>>(x, (int8_t*)p_qx, (float*)p_sx, CC);
    split_f32<<<(MKV * CC) / 256, 256>>>(cond, (__half*)p_ch, (__half*)p_cl, MKV * CC);
    split_f32<<<(CC * CC) / 256, 256>>>(wk, (__half*)p_wkh, (__half*)p_wkl, CC * CC);
    split_f32<<<(CC * CC) / 256, 256>>>(wv, (__half*)p_wvh, (__half*)p_wvl, CC * CC);

    // 2. Q projection (W8A8, int8 IMMA, exact) -> fp16 hi/lo planes w/ QFOLD
    gemm_tc<<<dim3(CC / 256, MTOK / 128), 256, GEMM_SMEM>>>(
        (const int8_t*)p_qx, (const int8_t*)p_qwq,
        (const float*)p_sx, (const float*)p_swq, bq, nullptr,
        (__half*)p_qh, (__half*)p_ql, QFOLD);

    // 3. K/V projections (fp16-split tensor) -> hi/lo planes directly
    gemm_kv_tc<<<dim3(CC / 128, MKV / 128, 2), 256, KV_SMEM>>>(bk, bv);

    // 4. tensor-core flash attention
    attn_tc<<<dim3(NN / 128, BB * HH), 256, ATT_SMEM>>>(mask);

    // 5. requant + O projection (int8 IMMA) into d_out
    quant_rows<<<MTOK, 256>>>((const float*)p_o, (int8_t*)p_qo, (float*)p_so, CC);
    gemm_tc<<<dim3(CC / 256, MTOK / 128), 256, GEMM_SMEM>>>(
        (const int8_t*)p_qo, (const int8_t*)p_qwo,
        (const float*)p_so, (const float*)p_swo, bo, out,
        nullptr, nullptr, 1.0f);
}

// round 16
// speedup vs baseline: 1.7390x; 1.7390x over previous
#include <cuda_runtime.h>
#include <cuda_bf16.h>
#include <cuda_fp16.h>
#include <math.h>
#include <stdint.h>

#define BB 2
#define NN 4096
#define LL 512
#define CC 2048
#define HH 16
#define DD 128
#define MTOK (BB*NN)
#define MKV  (BB*LL)
#define L2E  1.4426950408889634f
#define QFOLD (0.08838834764831845f * 1.4426950408889634f)  // inv_sqrt(128)*log2e

// -------------------- scratch ---------------------------------------------
__device__ __nv_bfloat16 g_qwq[(size_t)CC*CC];
__device__ float         g_swq[CC];
__device__ __nv_bfloat16 g_qwo[(size_t)CC*CC];
__device__ float         g_swo[CC];
__device__ __nv_bfloat16 g_qx[(size_t)MTOK*CC];
__device__ float         g_sx[MTOK];
__device__ float         g_o[(size_t)MTOK*CC];
__device__ __nv_bfloat16 g_qo[(size_t)MTOK*CC];
__device__ float         g_so[MTOK];
// fp16 hi/lo split planes
__device__ __half g_qh_[(size_t)MTOK*CC];
__device__ __half g_ql_[(size_t)MTOK*CC];
__device__ __half g_kh_[(size_t)MKV*CC];
__device__ __half g_kl_[(size_t)MKV*CC];
__device__ __half g_vh_[(size_t)MKV*CC];
__device__ __half g_vl_[(size_t)MKV*CC];
__device__ __half g_ch_[(size_t)MKV*CC];     // cond split
__device__ __half g_cl_[(size_t)MKV*CC];
__device__ __half g_wkh_[(size_t)CC*CC];
__device__ __half g_wkl_[(size_t)CC*CC];
__device__ __half g_wvh_[(size_t)CC*CC];
__device__ __half g_wvl_[(size_t)CC*CC];

// -------------------- helpers ---------------------------------------------
__device__ __forceinline__ uint32_t smem_u32(const void* p) {
    uint32_t a;
    asm("{ .reg .u64 t; cvta.to.shared.u64 t, %1; cvt.u32.u64 %0, t; }"
        : "=r"(a) : "l"(p));
    return a;
}
__device__ __forceinline__ void cp16(uint32_t dst, const void* src) {
    asm volatile("cp.async.cg.shared.global [%0], [%1], 16;" :: "r"(dst), "l"(src));
}
#define SW128(x) ((x) ^ (((x) >> 3) & 0x70))

#define LDSM4(r0, r1, r2, r3, addr) \
    asm volatile("ldmatrix.sync.aligned.m8n8.x4.shared.b16 {%0,%1,%2,%3}, [%4];" \
                 : "=r"(r0), "=r"(r1), "=r"(r2), "=r"(r3) : "r"(addr))
#define LDSM4T(r0, r1, r2, r3, addr) \
    asm volatile("ldmatrix.sync.aligned.m8n8.x4.trans.shared.b16 {%0,%1,%2,%3}, [%4];" \
                 : "=r"(r0), "=r"(r1), "=r"(r2), "=r"(r3) : "r"(addr))

__device__ __forceinline__ void mma16816(float* d,
    uint32_t a0, uint32_t a1, uint32_t a2, uint32_t a3, uint32_t b0, uint32_t b1)
{
    asm volatile(
        "mma.sync.aligned.m16n8k16.row.col.f32.bf16.bf16.f32 "
        "{%0,%1,%2,%3}, {%4,%5,%6,%7}, {%8,%9}, {%0,%1,%2,%3};"
        : "+f"(d[0]), "+f"(d[1]), "+f"(d[2]), "+f"(d[3])
        : "r"(a0), "r"(a1), "r"(a2), "r"(a3), "r"(b0), "r"(b1));
}
__device__ __forceinline__ void mma_h(float* d, const uint32_t* a,
                                      uint32_t b0, uint32_t b1)
{
    asm volatile(
        "mma.sync.aligned.m16n8k16.row.col.f32.f16.f16.f32 "
        "{%0,%1,%2,%3}, {%4,%5,%6,%7}, {%8,%9}, {%0,%1,%2,%3};"
        : "+f"(d[0]), "+f"(d[1]), "+f"(d[2]), "+f"(d[3])
        : "r"(a[0]), "r"(a[1]), "r"(a[2]), "r"(a[3]), "r"(b0), "r"(b1));
}

__device__ __forceinline__ float exp2_poly(float t) {
    t = fmaxf(t, -126.f);
    float fi = rintf(t);
    float f = t - fi;
    float p = 1.5403530e-4f;
    p = fmaf(p, f, 1.3333558e-3f);
    p = fmaf(p, f, 9.6181292e-3f);
    p = fmaf(p, f, 5.5504109e-2f);
    p = fmaf(p, f, 2.4022651e-1f);
    p = fmaf(p, f, 6.9314718e-1f);
    p = fmaf(p, f, 1.0f);
    return __uint_as_float(__float_as_uint(p) + ((int)fi << 23));
}
__device__ __forceinline__ uint32_t packh(float x, float y) {
    __half2 h = __halves2half2(__float2half_rn(x), __float2half_rn(y));
    return *(uint32_t*)&h;
}
__device__ __forceinline__ void split2(float x, float y, uint32_t& hi, uint32_t& lo) {
    __half hx = __float2half_rn(x), hy = __float2half_rn(y);
    __half lx = __float2half_rn(x - __half2float(hx));
    __half ly = __float2half_rn(y - __half2float(hy));
    __half2 h = __halves2half2(hx, hy);
    __half2 l = __halves2half2(lx, ly);
    hi = *(uint32_t*)&h;
    lo = *(uint32_t*)&l;
}

// -------------------- quant (single-pass, register-cached) -----------------
// K == CC == 2048: 256 threads x 8 floats/thread. One global read pass.
// Semantics identical: sc = max(max|x|/127, 1e-8); q = clip(rintf(x/sc)).
__global__ __launch_bounds__(256) void quant_rows(
    const float* __restrict__ src, __nv_bfloat16* __restrict__ qdst,
    float* __restrict__ sdst)
{
    int row = blockIdx.x;
    const float4* p = (const float4*)(src + (size_t)row * CC);
    float4 v0 = p[threadIdx.x];
    float4 v1 = p[threadIdx.x + 256];
    float m = fmaxf(fmaxf(fmaxf(fabsf(v0.x), fabsf(v0.y)),
                          fmaxf(fabsf(v0.z), fabsf(v0.w))),
                    fmaxf(fmaxf(fabsf(v1.x), fabsf(v1.y)),
                          fmaxf(fabsf(v1.z), fabsf(v1.w))));
    __shared__ float red[256];
    red[threadIdx.x] = m;
    __syncthreads();
    for (int s = 128; s > 0; s >>= 1) {
        if (threadIdx.x < s) red[threadIdx.x] = fmaxf(red[threadIdx.x], red[threadIdx.x + s]);
        __syncthreads();
    }
    float sc = fmaxf(red[0] / 127.0f, 1e-8f);

    __nv_bfloat16 q[8];
    float vv[8] = {v0.x, v0.y, v0.z, v0.w, v1.x, v1.y, v1.z, v1.w};
#pragma unroll
    for (int i = 0; i < 8; i++) {
        float r = rintf(vv[i] / sc);
        r = fminf(fmaxf(r, -127.f), 127.f);
        q[i] = __float2bfloat16(r);     // exact (|r| <= 127 integer)
    }
    uint2* qrow = (uint2*)(qdst + (size_t)row * CC);
    qrow[threadIdx.x]       = *(uint2*)&q[0];
    qrow[threadIdx.x + 256] = *(uint2*)&q[4];
    if (threadIdx.x == 0) sdst[row] = sc;
}

// -------------------- fp32 -> fp16 hi/lo split -----------------------------
__global__ void split_f32(const float* __restrict__ src, __half* __restrict__ h,
                          __half* __restrict__ l, int n) {
    int i = blockIdx.x * blockDim.x + threadIdx.x;
    if (i < n) {
        float x = src[i];
        __half hx = __float2half_rn(x);
        h[i] = hx;
        l[i] = __float2half_rn(x - __half2float(hx));
    }
}

// -------------------- bf16 W8A8 GEMM, CTA tile 128x256 --------------------
// out[m][n] = float(int32-exact acc) * (sa[m]*sw[n]) + bias[n]
// Split-output mode (outh != nullptr): writes fp16 hi/lo planes of y*fold.
#define GNST 3
#define GSTA 16384u                       // A plane: 128 rows x 128B
#define GSTB 32768u                       // B plane: 256 rows x 128B
#define GSTAGE_BYTES (GSTA + GSTB)        // 48KB
#define GSM_A(s) ((unsigned)(s) * GSTAGE_BYTES)
#define GSM_B(s) (GSM_A(s) + GSTA)
#define GEMM_SMEM (GNST * GSTAGE_BYTES)   // 144KB
#define GNCH (CC / 64)                    // 32 K-chunks

__device__ __forceinline__ void gemm_load_stage(
    uint32_t smem_base, int s, int ks, int m0, int n0, int tid,
    const __nv_bfloat16* __restrict__ A, const __nv_bfloat16* __restrict__ W)
{
    size_t coff = (size_t)ks * 64;
    uint32_t abase = smem_base + GSM_A(s);
    uint32_t bbase = smem_base + GSM_B(s);
#pragma unroll
    for (int j = 0; j < 4; j++) {          // A: 128 rows x 8 granules
        int g = tid + j * 256, r = g >> 3, i = g & 7;
        cp16(abase + SW128((uint32_t)(r * 128 + i * 16)),
             (const char*)(A + (size_t)(m0 + r) * CC + coff) + i * 16);
    }
#pragma unroll
    for (int j = 0; j < 8; j++) {          // B: 256 rows x 8 granules
        int g = tid + j * 256, r = g >> 3, i = g & 7;
        cp16(bbase + SW128((uint32_t)(r * 128 + i * 16)),
             (const char*)(W + (size_t)(n0 + r) * CC + coff) + i * 16);
    }
    asm volatile("cp.async.commit_group;" ::: "memory");
}

__global__ __launch_bounds__(256, 1) void gemm_tc(
    const __nv_bfloat16* __restrict__ A, const __nv_bfloat16* __restrict__ W,
    const float* __restrict__ sa, const float* __restrict__ sw,
    const float* __restrict__ bias, float* __restrict__ out,
    __half* __restrict__ outh, __half* __restrict__ outl, float fold)
{
    extern __shared__ char smem[];
    uint32_t sb = smem_u32(smem);
    int tid = threadIdx.x;
    int wid = tid >> 5, lid = tid & 31;
    int m0 = blockIdx.y * 128, n0 = blockIdx.x * 256;
    int wm = wid >> 2, wn = wid & 3;
    int lrow = (lid & 7) + ((lid >> 3) & 1) * 8;
    int lcol = (lid >> 4) * 16;

    float acc[4][8][4];
#pragma unroll
    for (int mt = 0; mt < 4; mt++)
#pragma unroll
        for (int nt = 0; nt < 8; nt++)
#pragma unroll
            for (int q = 0; q < 4; q++) acc[mt][nt][q] = 0.f;

    gemm_load_stage(sb, 0, 0, m0, n0, tid, A, W);
    gemm_load_stage(sb, 1, 1, m0, n0, tid, A, W);
    gemm_load_stage(sb, 2, 2, m0, n0, tid, A, W);

    int a_row = wm * 64 + lrow;
    int b_row = wn * 64 + lrow;

    for (int ks = 0; ks < GNCH; ks++) {
        int s = ks % GNST;
        if (ks < GNCH - 2)       asm volatile("cp.async.wait_group 2;" ::: "memory");
        else if (ks == GNCH - 2) asm volatile("cp.async.wait_group 1;" ::: "memory");
        else                     asm volatile("cp.async.wait_group 0;" ::: "memory");
        __syncthreads();
        uint32_t abase = sb + GSM_A(s);
        uint32_t bbase = sb + GSM_B(s);
#pragma unroll
        for (int kt = 0; kt < 4; kt++) {
            int kb = kt * 32 + lcol;
            uint32_t af[4][4];
#pragma unroll
            for (int mt = 0; mt < 4; mt++)
                LDSM4(af[mt][0], af[mt][1], af[mt][2], af[mt][3],
                      abase + SW128((uint32_t)((a_row + mt * 16) * 128 + kb)));
            uint32_t bf[4][4];
#pragma unroll
            for (int np = 0; np < 4; np++)
                LDSM4(bf[np][0], bf[np][1], bf[np][2], bf[np][3],
                      bbase + SW128((uint32_t)((b_row + np * 16) * 128 + kb)));
#pragma unroll
            for (int mt = 0; mt < 4; mt++)
#pragma unroll
                for (int np = 0; np < 4; np++) {
                    mma16816(acc[mt][np * 2 + 0], af[mt][0], af[mt][1], af[mt][2], af[mt][3],
                             bf[np][0], bf[np][2]);
                    mma16816(acc[mt][np * 2 + 1], af[mt][0], af[mt][1], af[mt][2], af[mt][3],
                             bf[np][1], bf[np][3]);
                }
        }
        __syncthreads();
        if (ks + GNST < GNCH)
            gemm_load_stage(sb, s, ks + GNST, m0, n0, tid, A, W);
    }

    int g = lid >> 2, t = lid & 3;
#pragma unroll
    for (int mt = 0; mt < 4; mt++) {
        int mA = m0 + wm * 64 + mt * 16 + g;
        int mB = mA + 8;
        float saA = sa[mA], saB = sa[mB];
#pragma unroll
        for (int nt = 0; nt < 8; nt++) {
            int n = n0 + wn * 64 + (nt >> 1) * 16 + (nt & 1) * 8 + t * 2;
            float2 vsw = *(const float2*)(sw + n);
            float2 vbi = *(const float2*)(bias + n);
            float yA0 = acc[mt][nt][0] * (saA * vsw.x) + vbi.x;
            float yA1 = acc[mt][nt][1] * (saA * vsw.y) + vbi.y;
            float yB0 = acc[mt][nt][2] * (saB * vsw.x) + vbi.x;
            float yB1 = acc[mt][nt][3] * (saB * vsw.y) + vbi.y;
            if (outh) {
                uint32_t hA, lA, hB, lB;
                split2(yA0 * fold, yA1 * fold, hA, lA);
                split2(yB0 * fold, yB1 * fold, hB, lB);
                *(uint32_t*)(outh + (size_t)mA * CC + n) = hA;
                *(uint32_t*)(outl + (size_t)mA * CC + n) = lA;
                *(uint32_t*)(outh + (size_t)mB * CC + n) = hB;
                *(uint32_t*)(outl + (size_t)mB * CC + n) = lB;
            } else {
                *(float2*)(out + (size_t)mA * CC + n) = make_float2(yA0, yA1);
                *(float2*)(out + (size_t)mB * CC + n) = make_float2(yB0, yB1);
            }
        }
    }
}

// -------------------- fp16-split tensor GEMM for K/V projections -----------
#define KVPL 16384u
#define KVSTAGE (4u * KVPL)             // Ah Al Bh Bl = 64KB
#define KV_SMEM (2u * KVSTAGE)          // 128KB, 2 stages
#define KVNCH (CC / 64)

__device__ __forceinline__ void kv_load_stage(
    uint32_t sbase, int s, int ks, int m0, int n0, int tid,
    const __half* __restrict__ Bh, const __half* __restrict__ Bl)
{
    size_t coff = (size_t)ks * 64;
    uint32_t st = sbase + (uint32_t)s * KVSTAGE;
#pragma unroll
    for (int j = 0; j < 16; j++) {
        int gi = tid + j * 256;
        int plane = gi >> 10;            // 0:Ah 1:Al 2:Bh 3:Bl
        int within = gi & 1023;
        int r = within >> 3, i = within & 7;
        const __half* arr = (plane == 0) ? g_ch_ : (plane == 1) ? g_cl_
                          : (plane == 2) ? Bh : Bl;
        int row = (plane < 2 ? m0 : n0) + r;
        cp16(st + (uint32_t)plane * KVPL + SW128((uint32_t)(r * 128 + i * 16)),
             arr + (size_t)row * CC + coff + i * 8);
    }
    asm volatile("cp.async.commit_group;" ::: "memory");
}

__global__ __launch_bounds__(256, 1) void gemm_kv_tc(
    const float* __restrict__ bk, const float* __restrict__ bv)
{
    extern __shared__ char smem[];
    uint32_t sb = smem_u32(smem);
    int tid = threadIdx.x;
    int wid = tid >> 5, lid = tid & 31;
    int m0 = blockIdx.y * 128, n0 = blockIdx.x * 128;
    int wm = wid >> 2, wn = wid & 3;
    int z = blockIdx.z;
    const __half* Bh = z ? g_wvh_ : g_wkh_;
    const __half* Bl = z ? g_wvl_ : g_wkl_;
    const float* bias = z ? bv : bk;
    __half* outh = z ? g_vh_ : g_kh_;
    __half* outl = z ? g_vl_ : g_kl_;

    int lrow = (lid & 7) + ((lid >> 3) & 1) * 8;
    int lcol = (lid >> 4) * 16;

    float acc[4][4][4];
#pragma unroll
    for (int mt = 0; mt < 4; mt++)
#pragma unroll
        for (int nt = 0; nt < 4; nt++)
#pragma unroll
            for (int q = 0; q < 4; q++) acc[mt][nt][q] = 0.f;

    kv_load_stage(sb, 0, 0, m0, n0, tid, Bh, Bl);
    kv_load_stage(sb, 1, 1, m0, n0, tid, Bh, Bl);

    int a_row = wm * 64 + lrow;
    int b_row = wn * 32 + lrow;

    for (int ks = 0; ks < KVNCH; ks++) {
        int s = ks & 1;
        if (ks < KVNCH - 1) asm volatile("cp.async.wait_group 1;" ::: "memory");
        else                asm volatile("cp.async.wait_group 0;" ::: "memory");
        __syncthreads();
        uint32_t st = sb + (uint32_t)s * KVSTAGE;
#pragma unroll
        for (int kt = 0; kt < 4; kt++) {
            int kb = kt * 32 + lcol;
            uint32_t ah[4][4], al_[4][4];
#pragma unroll
            for (int mt = 0; mt < 4; mt++) {
                uint32_t ro = SW128((uint32_t)((a_row + mt * 16) * 128 + kb));
                LDSM4(ah[mt][0], ah[mt][1], ah[mt][2], ah[mt][3], st + ro);
                LDSM4(al_[mt][0], al_[mt][1], al_[mt][2], al_[mt][3], st + KVPL + ro);
            }
            uint32_t bh[2][4], bl_[2][4];
#pragma unroll
            for (int np = 0; np < 2; np++) {
                uint32_t ro = SW128((uint32_t)((b_row + np * 16) * 128 + kb));
                LDSM4(bh[np][0], bh[np][1], bh[np][2], bh[np][3], st + 2u * KVPL + ro);
                LDSM4(bl_[np][0], bl_[np][1], bl_[np][2], bl_[np][3], st + 3u * KVPL + ro);
            }
#pragma unroll
            for (int mt = 0; mt < 4; mt++)
#pragma unroll
                for (int np = 0; np < 2; np++) {
                    mma_h(acc[mt][np * 2 + 0], ah[mt],  bh[np][0],  bh[np][2]);
                    mma_h(acc[mt][np * 2 + 0], ah[mt],  bl_[np][0], bl_[np][2]);
                    mma_h(acc[mt][np * 2 + 0], al_[mt], bh[np][0],  bh[np][2]);
                    mma_h(acc[mt][np * 2 + 1], ah[mt],  bh[np][1],  bh[np][3]);
                    mma_h(acc[mt][np * 2 + 1], ah[mt],  bl_[np][1], bl_[np][3]);
                    mma_h(acc[mt][np * 2 + 1], al_[mt], bh[np][1],  bh[np][3]);
                }
        }
        __syncthreads();
        if (ks + 2 < KVNCH)
            kv_load_stage(sb, s, ks + 2, m0, n0, tid, Bh, Bl);
    }

    int g = lid >> 2, t = lid & 3;
#pragma unroll
    for (int mt = 0; mt < 4; mt++) {
        int mA = m0 + wm * 64 + mt * 16 + g;
        int mB = mA + 8;
#pragma unroll
        for (int nt = 0; nt < 4; nt++) {
            int n = n0 + wn * 32 + nt * 8 + t * 2;
            float2 vbi = *(const float2*)(bias + n);
            uint32_t hA, lA, hB, lB;
            split2(acc[mt][nt][0] + vbi.x, acc[mt][nt][1] + vbi.y, hA, lA);
            split2(acc[mt][nt][2] + vbi.x, acc[mt][nt][3] + vbi.y, hB, lB);
            *(uint32_t*)(outh + (size_t)mA * CC + n) = hA;
            *(uint32_t*)(outl + (size_t)mA * CC + n) = lA;
            *(uint32_t*)(outh + (size_t)mB * CC + n) = hB;
            *(uint32_t*)(outl + (size_t)mB * CC + n) = lB;
        }
    }
}

// -------------------- fp16-split tensor-core flash attention ---------------
#define ATT_SMEM (192*1024)

__device__ __forceinline__ void attn_load_kv(uint32_t base, int chunk,
                                             int b, int h, int tid) {
    size_t rowbase = (size_t)b * LL + chunk * 64;
#pragma unroll
    for (int j = 0; j < 16; j++) {
        int gi = tid + j * 256;
        int plane = gi >> 9;
        int within = gi & 511;
        int r = within >> 3, i = within & 7;
        const __half* arr = (plane < 2) ? g_kh_ : (plane < 4) ? g_kl_
                          : (plane < 6) ? g_vh_ : g_vl_;
        cp16(base + (uint32_t)plane * 8192u + SW128((uint32_t)(r * 128 + i * 16)),
             arr + (rowbase + r) * CC + h * DD + (plane & 1) * 64 + i * 8);
    }
    asm volatile("cp.async.commit_group;" ::: "memory");
}

__global__ __launch_bounds__(256, 1) void attn_tc(const float* __restrict__ mask)
{
    extern __shared__ char smem[];
    uint32_t sb = smem_u32(smem);
    int tid = threadIdx.x;
    int wid = tid >> 5, lid = tid & 31;
    int b = blockIdx.y >> 4, h = blockIdx.y & 15;
    int n0 = blockIdx.x * 128;
    int lrow = (lid & 7) + ((lid >> 3) & 1) * 8;
    int lcol = (lid >> 4) * 16;
    int g = lid >> 2, t = lid & 3;

    {
        size_t rowbase = (size_t)b * NN + n0;
#pragma unroll
        for (int j = 0; j < 16; j++) {
            int gi = tid + j * 256;
            int plane = gi >> 10;
            int within = gi & 1023;
            int r = within >> 3, i = within & 7;
            const __half* arr = (plane < 2) ? g_qh_ : g_ql_;
            cp16(sb + (uint32_t)plane * 16384u + SW128((uint32_t)(r * 128 + i * 16)),
                 arr + (rowbase + r) * CC + h * DD + (plane & 1) * 64 + i * 8);
        }
        asm volatile("cp.async.commit_group;" ::: "memory");
    }
    attn_load_kv(sb + 65536u, 0, b, h, tid);

    asm volatile("cp.async.wait_group 1;" ::: "memory");
    __syncthreads();
    uint32_t qh_f[8][4], ql_f[8][4];
#pragma unroll
    for (int kt = 0; kt < 8; kt++) {
        uint32_t ro = SW128((uint32_t)((wid * 16 + lrow) * 128 + (kt & 3) * 32 + lcol));
        uint32_t ph = (uint32_t)(kt >> 2) * 16384u;
        LDSM4(qh_f[kt][0], qh_f[kt][1], qh_f[kt][2], qh_f[kt][3], sb + ph + ro);
        LDSM4(ql_f[kt][0], ql_f[kt][1], ql_f[kt][2], ql_f[kt][3], sb + 32768u + ph + ro);
    }
    __syncthreads();
    attn_load_kv(sb, 1, b, h, tid);

    float m0r = -INFINITY, m1r = -INFINITY, l0r = 0.f, l1r = 0.f;
    float oacc[16][4];
#pragma unroll
    for (int j = 0; j < 16; j++)
#pragma unroll
        for (int q = 0; q < 4; q++) oacc[j][q] = 0.f;

    const float* mr0 = mask + ((size_t)b * NN + n0 + wid * 16 + g) * LL + 2 * t;
    const float* mr1 = mr0 + 8 * LL;

    for (int c = 0; c < LL / 64; c++) {
        uint32_t kvb = (c & 1) ? sb : (sb + 65536u);
        if (c < LL / 64 - 1) asm volatile("cp.async.wait_group 1;" ::: "memory");
        else                 asm volatile("cp.async.wait_group 0;" ::: "memory");
        __syncthreads();

        float sacc[8][4];
#pragma unroll
        for (int j = 0; j < 8; j++) {
            float2 a = *(const float2*)(mr0 + c * 64 + j * 8);
            float2 d = *(const float2*)(mr1 + c * 64 + j * 8);
            sacc[j][0] = a.x * L2E; sacc[j][1] = a.y * L2E;
            sacc[j][2] = d.x * L2E; sacc[j][3] = d.y * L2E;
        }
#pragma unroll
        for (int kt = 0; kt < 8; kt++) {
            uint32_t pk = (uint32_t)(kt >> 2) * 8192u;
            uint32_t kb = (uint32_t)((kt & 3) * 32 + lcol);
#pragma unroll
            for (int j16 = 0; j16 < 4; j16++) {
                uint32_t ro = SW128((uint32_t)((j16 * 16 + lrow) * 128) + kb);
                uint32_t kh0, kh1, kh2, kh3, kl0, kl1, kl2, kl3;
                LDSM4(kh0, kh1, kh2, kh3, kvb + pk + ro);
                LDSM4(kl0, kl1, kl2, kl3, kvb + 16384u + pk + ro);
                mma_h(sacc[2 * j16],     qh_f[kt], kh0, kh2);
                mma_h(sacc[2 * j16],     qh_f[kt], kl0, kl2);
                mma_h(sacc[2 * j16],     ql_f[kt], kh0, kh2);
                mma_h(sacc[2 * j16 + 1], qh_f[kt], kh1, kh3);
                mma_h(sacc[2 * j16 + 1], qh_f[kt], kl1, kl3);
                mma_h(sacc[2 * j16 + 1], ql_f[kt], kh1, kh3);
            }
        }

        float mx0 = -INFINITY, mx1 = -INFINITY;
#pragma unroll
        for (int j = 0; j < 8; j++) {
            mx0 = fmaxf(mx0, fmaxf(sacc[j][0], sacc[j][1]));
            mx1 = fmaxf(mx1, fmaxf(sacc[j][2], sacc[j][3]));
        }
#pragma unroll
        for (int off = 1; off < 4; off <<= 1) {
            mx0 = fmaxf(mx0, __shfl_xor_sync(0xffffffffu, mx0, off));
            mx1 = fmaxf(mx1, __shfl_xor_sync(0xffffffffu, mx1, off));
        }
        float nm0 = fmaxf(m0r, mx0), nm1 = fmaxf(m1r, mx1);
        float cr0 = exp2_poly(m0r - nm0), cr1 = exp2_poly(m1r - nm1);
        m0r = nm0; m1r = nm1;

        uint32_t pa_h[4][4], pa_l[4][4];
        float rs0 = 0.f, rs1 = 0.f;
#pragma unroll
        for (int j = 0; j < 8; j++) {
            float p0 = exp2_poly(sacc[j][0] - nm0);
            float p1 = exp2_poly(sacc[j][1] - nm0);
            float p2 = exp2_poly(sacc[j][2] - nm1);
            float p3 = exp2_poly(sacc[j][3] - nm1);
            rs0 += p0 + p1; rs1 += p2 + p3;
            uint32_t h01 = packh(p0, p1), h23 = packh(p2, p3);
            __half2 hh01 = *(__half2*)&h01, hh23 = *(__half2*)&h23;
            uint32_t l01 = packh(p0 - __low2float(hh01),  p1 - __high2float(hh01));
            uint32_t l23 = packh(p2 - __low2float(hh23),  p3 - __high2float(hh23));
            int kt2 = j >> 1, sl = (j & 1) * 2;
            pa_h[kt2][sl] = h01; pa_h[kt2][sl + 1] = h23;
            pa_l[kt2][sl] = l01; pa_l[kt2][sl + 1] = l23;
        }
#pragma unroll
        for (int off = 1; off < 4; off <<= 1) {
            rs0 += __shfl_xor_sync(0xffffffffu, rs0, off);
            rs1 += __shfl_xor_sync(0xffffffffu, rs1, off);
        }
        l0r = l0r * cr0 + rs0;
        l1r = l1r * cr1 + rs1;
#pragma unroll
        for (int j = 0; j < 16; j++) {
            oacc[j][0] *= cr0; oacc[j][1] *= cr0;
            oacc[j][2] *= cr1; oacc[j][3] *= cr1;
        }

#pragma unroll
        for (int lt = 0; lt < 4; lt++) {
#pragma unroll
            for (int dq = 0; dq < 8; dq++) {
                uint32_t pv = (uint32_t)(4 + (dq >> 2)) * 8192u;
                uint32_t ro = SW128((uint32_t)((lt * 16 + lrow) * 128 + (dq & 3) * 32 + lcol));
                uint32_t vh0, vh1, vh2, vh3, vl0, vl1, vl2, vl3;
                LDSM4T(vh0, vh1, vh2, vh3, kvb + pv + ro);
                LDSM4T(vl0, vl1, vl2, vl3, kvb + 16384u + pv + ro);
                mma_h(oacc[2 * dq],     pa_h[lt], vh0, vh1);
                mma_h(oacc[2 * dq],     pa_h[lt], vl0, vl1);
                mma_h(oacc[2 * dq],     pa_l[lt], vh0, vh1);
                mma_h(oacc[2 * dq + 1], pa_h[lt], vh2, vh3);
                mma_h(oacc[2 * dq + 1], pa_h[lt], vl2, vl3);
                mma_h(oacc[2 * dq + 1], pa_l[lt], vh2, vh3);
            }
        }
        __syncthreads();
        if (c + 2 < LL / 64)
            attn_load_kv(kvb, c + 2, b, h, tid);
    }

    float inv0 = 1.f / l0r, inv1 = 1.f / l1r;
    float* o0 = g_o + ((size_t)b * NN + n0 + wid * 16 + g) * CC + h * DD + 2 * t;
    float* o1 = o0 + 8 * (size_t)CC;
#pragma unroll
    for (int dn = 0; dn < 16; dn++) {
        *(float2*)(o0 + dn * 8) = make_float2(oacc[dn][0] * inv0, oacc[dn][1] * inv0);
        *(float2*)(o1 + dn * 8) = make_float2(oacc[dn][2] * inv1, oacc[dn][3] * inv1);
    }
}

// -------------------- launcher --------------------------------------------
extern "C" void kernel_launch(void* const* d_in, const int* in_sizes, int n_in,
                              void* d_out, int out_size) {
    const float* x    = (const float*)d_in[0];
    const float* cond = (const float*)d_in[1];
    const float* mask = (const float*)d_in[2];
    const float* wq   = (const float*)d_in[3];
    const float* bq   = (const float*)d_in[4];
    const float* wk   = (const float*)d_in[5];
    const float* bk   = (const float*)d_in[6];
    const float* wv   = (const float*)d_in[7];
    const float* bv   = (const float*)d_in[8];
    const float* wo   = (const float*)d_in[9];
    const float* bo   = (const float*)d_in[10];
    float* out = (float*)d_out;

    void *p_qwq, *p_swq, *p_qwo, *p_swo, *p_qx, *p_sx, *p_o, *p_qo, *p_so;
    void *p_qh, *p_ql, *p_ch, *p_cl, *p_wkh, *p_wkl, *p_wvh, *p_wvl;
    cudaGetSymbolAddress(&p_qwq, g_qwq);
    cudaGetSymbolAddress(&p_swq, g_swq);
    cudaGetSymbolAddress(&p_qwo, g_qwo);
    cudaGetSymbolAddress(&p_swo, g_swo);
    cudaGetSymbolAddress(&p_qx,  g_qx);
    cudaGetSymbolAddress(&p_sx,  g_sx);
    cudaGetSymbolAddress(&p_o,   g_o);
    cudaGetSymbolAddress(&p_qo,  g_qo);
    cudaGetSymbolAddress(&p_so,  g_so);
    cudaGetSymbolAddress(&p_qh,  g_qh_);
    cudaGetSymbolAddress(&p_ql,  g_ql_);
    cudaGetSymbolAddress(&p_ch,  g_ch_);
    cudaGetSymbolAddress(&p_cl,  g_cl_);
    cudaGetSymbolAddress(&p_wkh, g_wkh_);
    cudaGetSymbolAddress(&p_wkl, g_wkl_);
    cudaGetSymbolAddress(&p_wvh, g_wvh_);
    cudaGetSymbolAddress(&p_wvl, g_wvl_);

    cudaFuncSetAttribute(gemm_tc,
                         cudaFuncAttributeMaxDynamicSharedMemorySize, GEMM_SMEM);
    cudaFuncSetAttribute(gemm_kv_tc,
                         cudaFuncAttributeMaxDynamicSharedMemorySize, KV_SMEM);
    cudaFuncSetAttribute(attn_tc,
                         cudaFuncAttributeMaxDynamicSharedMemorySize, ATT_SMEM);

    // 1. quantize weights + activations (single-pass); split cond + K/V weights
    quant_rows<<<CC, 256>>>(wq, (__nv_bfloat16*)p_qwq, (float*)p_swq);
    quant_rows<<<CC, 256>>>(wo, (__nv_bfloat16*)p_qwo, (float*)p_swo);
    quant_rows<<<MTOK, 256>>>(x, (__nv_bfloat16*)p_qx, (float*)p_sx);
    split_f32<<<(MKV * CC) / 256, 256>>>(cond, (__half*)p_ch, (__half*)p_cl, MKV * CC);
    split_f32<<<(CC * CC) / 256, 256>>>(wk, (__half*)p_wkh, (__half*)p_wkl, CC * CC);
    split_f32<<<(CC * CC) / 256, 256>>>(wv, (__half*)p_wvh, (__half*)p_wvl, CC * CC);

    // 2. Q projection (W8A8, int32-exact bf16 mma) -> fp16 hi/lo planes w/ QFOLD
    gemm_tc<<<dim3(CC / 256, MTOK / 128), 256, GEMM_SMEM>>>(
        (const __nv_bfloat16*)p_qx, (const __nv_bfloat16*)p_qwq,
        (const float*)p_sx, (const float*)p_swq, bq, nullptr,
        (__half*)p_qh, (__half*)p_ql, QFOLD);

    // 3. K/V projections (fp16-split tensor) -> hi/lo planes directly
    gemm_kv_tc<<<dim3(CC / 128, MKV / 128, 2), 256, KV_SMEM>>>(bk, bv);

    // 4. tensor-core flash attention
    attn_tc<<<dim3(NN / 128, BB * HH), 256, ATT_SMEM>>>(mask);

    // 5. requant + O projection into d_out
    quant_rows<<<MTOK, 256>>>((const float*)p_o, (__nv_bfloat16*)p_qo, (float*)p_so);
    gemm_tc<<<dim3(CC / 256, MTOK / 128), 256, GEMM_SMEM>>>(
        (const __nv_bfloat16*)p_qo, (const __nv_bfloat16*)p_qwo,
        (const float*)p_so, (const float*)p_swo, bo, out,
        nullptr, nullptr, 1.0f);
}

// round 17
// speedup vs baseline: 1.7550x; 1.0092x over previous
#include <cuda_runtime.h>
#include <cuda_bf16.h>
#include <cuda_fp16.h>
#include <math.h>
#include <stdint.h>

#define BB 2
#define NN 4096
#define LL 512
#define CC 2048
#define HH 16
#define DD 128
#define MTOK (BB*NN)
#define MKV  (BB*LL)
#define L2E  1.4426950408889634f
#define QFOLD (0.08838834764831845f * 1.4426950408889634f)  // inv_sqrt(128)*log2e

// -------------------- scratch ---------------------------------------------
__device__ __nv_bfloat16 g_qwq[(size_t)CC*CC];
__device__ float         g_swq[CC];
__device__ __nv_bfloat16 g_qwo[(size_t)CC*CC];
__device__ float         g_swo[CC];
__device__ __nv_bfloat16 g_qx[(size_t)MTOK*CC];
__device__ float         g_sx[MTOK];
__device__ float         g_o[(size_t)MTOK*CC];
__device__ __nv_bfloat16 g_qo[(size_t)MTOK*CC];
__device__ float         g_so[MTOK];
// fp16 hi/lo split planes
__device__ __half g_qh_[(size_t)MTOK*CC];
__device__ __half g_ql_[(size_t)MTOK*CC];
__device__ __half g_kh_[(size_t)MKV*CC];
__device__ __half g_kl_[(size_t)MKV*CC];
__device__ __half g_vh_[(size_t)MKV*CC];
__device__ __half g_vl_[(size_t)MKV*CC];
__device__ __half g_ch_[(size_t)MKV*CC];     // cond split
__device__ __half g_cl_[(size_t)MKV*CC];
__device__ __half g_wkh_[(size_t)CC*CC];
__device__ __half g_wkl_[(size_t)CC*CC];
__device__ __half g_wvh_[(size_t)CC*CC];
__device__ __half g_wvl_[(size_t)CC*CC];

// -------------------- helpers ---------------------------------------------
__device__ __forceinline__ uint32_t smem_u32(const void* p) {
    uint32_t a;
    asm("{ .reg .u64 t; cvta.to.shared.u64 t, %1; cvt.u32.u64 %0, t; }"
        : "=r"(a) : "l"(p));
    return a;
}
__device__ __forceinline__ void cp16(uint32_t dst, const void* src) {
    asm volatile("cp.async.cg.shared.global [%0], [%1], 16;" :: "r"(dst), "l"(src));
}
#define SW128(x) ((x) ^ (((x) >> 3) & 0x70))

#define LDSM4(r0, r1, r2, r3, addr) \
    asm volatile("ldmatrix.sync.aligned.m8n8.x4.shared.b16 {%0,%1,%2,%3}, [%4];" \
                 : "=r"(r0), "=r"(r1), "=r"(r2), "=r"(r3) : "r"(addr))
#define LDSM4T(r0, r1, r2, r3, addr) \
    asm volatile("ldmatrix.sync.aligned.m8n8.x4.trans.shared.b16 {%0,%1,%2,%3}, [%4];" \
                 : "=r"(r0), "=r"(r1), "=r"(r2), "=r"(r3) : "r"(addr))

__device__ __forceinline__ void mma16816(float* d,
    uint32_t a0, uint32_t a1, uint32_t a2, uint32_t a3, uint32_t b0, uint32_t b1)
{
    asm volatile(
        "mma.sync.aligned.m16n8k16.row.col.f32.bf16.bf16.f32 "
        "{%0,%1,%2,%3}, {%4,%5,%6,%7}, {%8,%9}, {%0,%1,%2,%3};"
        : "+f"(d[0]), "+f"(d[1]), "+f"(d[2]), "+f"(d[3])
        : "r"(a0), "r"(a1), "r"(a2), "r"(a3), "r"(b0), "r"(b1));
}
__device__ __forceinline__ void mma_h(float* d, const uint32_t* a,
                                      uint32_t b0, uint32_t b1)
{
    asm volatile(
        "mma.sync.aligned.m16n8k16.row.col.f32.f16.f16.f32 "
        "{%0,%1,%2,%3}, {%4,%5,%6,%7}, {%8,%9}, {%0,%1,%2,%3};"
        : "+f"(d[0]), "+f"(d[1]), "+f"(d[2]), "+f"(d[3])
        : "r"(a[0]), "r"(a[1]), "r"(a[2]), "r"(a[3]), "r"(b0), "r"(b1));
}

__device__ __forceinline__ float exp2_poly(float t) {
    t = fmaxf(t, -126.f);
    float fi = rintf(t);
    float f = t - fi;
    float p = 1.5403530e-4f;
    p = fmaf(p, f, 1.3333558e-3f);
    p = fmaf(p, f, 9.6181292e-3f);
    p = fmaf(p, f, 5.5504109e-2f);
    p = fmaf(p, f, 2.4022651e-1f);
    p = fmaf(p, f, 6.9314718e-1f);
    p = fmaf(p, f, 1.0f);
    return __uint_as_float(__float_as_uint(p) + ((int)fi << 23));
}
__device__ __forceinline__ uint32_t packh(float x, float y) {
    __half2 h = __halves2half2(__float2half_rn(x), __float2half_rn(y));
    return *(uint32_t*)&h;
}
__device__ __forceinline__ void split2(float x, float y, uint32_t& hi, uint32_t& lo) {
    __half hx = __float2half_rn(x), hy = __float2half_rn(y);
    __half lx = __float2half_rn(x - __half2float(hx));
    __half ly = __float2half_rn(y - __half2float(hy));
    __half2 h = __halves2half2(hx, hy);
    __half2 l = __halves2half2(lx, ly);
    hi = *(uint32_t*)&h;
    lo = *(uint32_t*)&l;
}

// -------------------- quant (single-pass, register-cached) -----------------
__global__ __launch_bounds__(256) void quant_rows(
    const float* __restrict__ src, __nv_bfloat16* __restrict__ qdst,
    float* __restrict__ sdst)
{
    int row = blockIdx.x;
    const float4* p = (const float4*)(src + (size_t)row * CC);
    float4 v0 = p[threadIdx.x];
    float4 v1 = p[threadIdx.x + 256];
    float m = fmaxf(fmaxf(fmaxf(fabsf(v0.x), fabsf(v0.y)),
                          fmaxf(fabsf(v0.z), fabsf(v0.w))),
                    fmaxf(fmaxf(fabsf(v1.x), fabsf(v1.y)),
                          fmaxf(fabsf(v1.z), fabsf(v1.w))));
    __shared__ float red[256];
    red[threadIdx.x] = m;
    __syncthreads();
    for (int s = 128; s > 0; s >>= 1) {
        if (threadIdx.x < s) red[threadIdx.x] = fmaxf(red[threadIdx.x], red[threadIdx.x + s]);
        __syncthreads();
    }
    float sc = fmaxf(red[0] / 127.0f, 1e-8f);

    __nv_bfloat16 q[8];
    float vv[8] = {v0.x, v0.y, v0.z, v0.w, v1.x, v1.y, v1.z, v1.w};
#pragma unroll
    for (int i = 0; i < 8; i++) {
        float r = rintf(vv[i] / sc);
        r = fminf(fmaxf(r, -127.f), 127.f);
        q[i] = __float2bfloat16(r);     // exact (|r| <= 127 integer)
    }
    uint2* qrow = (uint2*)(qdst + (size_t)row * CC);
    qrow[threadIdx.x]       = *(uint2*)&q[0];
    qrow[threadIdx.x + 256] = *(uint2*)&q[4];
    if (threadIdx.x == 0) sdst[row] = sc;
}

// -------------------- fp32 -> fp16 hi/lo split -----------------------------
__global__ void split_f32(const float* __restrict__ src, __half* __restrict__ h,
                          __half* __restrict__ l, int n) {
    int i = blockIdx.x * blockDim.x + threadIdx.x;
    if (i < n) {
        float x = src[i];
        __half hx = __float2half_rn(x);
        h[i] = hx;
        l[i] = __float2half_rn(x - __half2float(hx));
    }
}

// -------------------- bf16 W8A8 GEMM, CTA tile 128x256 --------------------
#define GNST 3
#define GSTA 16384u
#define GSTB 32768u
#define GSTAGE_BYTES (GSTA + GSTB)        // 48KB
#define GSM_A(s) ((unsigned)(s) * GSTAGE_BYTES)
#define GSM_B(s) (GSM_A(s) + GSTA)
#define GEMM_SMEM (GNST * GSTAGE_BYTES)   // 144KB
#define GNCH (CC / 64)

__device__ __forceinline__ void gemm_load_stage(
    uint32_t smem_base, int s, int ks, int m0, int n0, int tid,
    const __nv_bfloat16* __restrict__ A, const __nv_bfloat16* __restrict__ W)
{
    size_t coff = (size_t)ks * 64;
    uint32_t abase = smem_base + GSM_A(s);
    uint32_t bbase = smem_base + GSM_B(s);
#pragma unroll
    for (int j = 0; j < 4; j++) {
        int g = tid + j * 256, r = g >> 3, i = g & 7;
        cp16(abase + SW128((uint32_t)(r * 128 + i * 16)),
             (const char*)(A + (size_t)(m0 + r) * CC + coff) + i * 16);
    }
#pragma unroll
    for (int j = 0; j < 8; j++) {
        int g = tid + j * 256, r = g >> 3, i = g & 7;
        cp16(bbase + SW128((uint32_t)(r * 128 + i * 16)),
             (const char*)(W + (size_t)(n0 + r) * CC + coff) + i * 16);
    }
    asm volatile("cp.async.commit_group;" ::: "memory");
}

__global__ __launch_bounds__(256, 1) void gemm_tc(
    const __nv_bfloat16* __restrict__ A, const __nv_bfloat16* __restrict__ W,
    const float* __restrict__ sa, const float* __restrict__ sw,
    const float* __restrict__ bias, float* __restrict__ out,
    __half* __restrict__ outh, __half* __restrict__ outl, float fold)
{
    extern __shared__ char smem[];
    uint32_t sb = smem_u32(smem);
    int tid = threadIdx.x;
    int wid = tid >> 5, lid = tid & 31;
    int m0 = blockIdx.y * 128, n0 = blockIdx.x * 256;
    int wm = wid >> 2, wn = wid & 3;
    int lrow = (lid & 7) + ((lid >> 3) & 1) * 8;
    int lcol = (lid >> 4) * 16;

    float acc[4][8][4];
#pragma unroll
    for (int mt = 0; mt < 4; mt++)
#pragma unroll
        for (int nt = 0; nt < 8; nt++)
#pragma unroll
            for (int q = 0; q < 4; q++) acc[mt][nt][q] = 0.f;

    gemm_load_stage(sb, 0, 0, m0, n0, tid, A, W);
    gemm_load_stage(sb, 1, 1, m0, n0, tid, A, W);
    gemm_load_stage(sb, 2, 2, m0, n0, tid, A, W);

    int a_row = wm * 64 + lrow;
    int b_row = wn * 64 + lrow;

    for (int ks = 0; ks < GNCH; ks++) {
        int s = ks % GNST;
        if (ks < GNCH - 2)       asm volatile("cp.async.wait_group 2;" ::: "memory");
        else if (ks == GNCH - 2) asm volatile("cp.async.wait_group 1;" ::: "memory");
        else                     asm volatile("cp.async.wait_group 0;" ::: "memory");
        __syncthreads();
        uint32_t abase = sb + GSM_A(s);
        uint32_t bbase = sb + GSM_B(s);
#pragma unroll
        for (int kt = 0; kt < 4; kt++) {
            int kb = kt * 32 + lcol;
            uint32_t af[4][4];
#pragma unroll
            for (int mt = 0; mt < 4; mt++)
                LDSM4(af[mt][0], af[mt][1], af[mt][2], af[mt][3],
                      abase + SW128((uint32_t)((a_row + mt * 16) * 128 + kb)));
            uint32_t bf[4][4];
#pragma unroll
            for (int np = 0; np < 4; np++)
                LDSM4(bf[np][0], bf[np][1], bf[np][2], bf[np][3],
                      bbase + SW128((uint32_t)((b_row + np * 16) * 128 + kb)));
#pragma unroll
            for (int mt = 0; mt < 4; mt++)
#pragma unroll
                for (int np = 0; np < 4; np++) {
                    mma16816(acc[mt][np * 2 + 0], af[mt][0], af[mt][1], af[mt][2], af[mt][3],
                             bf[np][0], bf[np][2]);
                    mma16816(acc[mt][np * 2 + 1], af[mt][0], af[mt][1], af[mt][2], af[mt][3],
                             bf[np][1], bf[np][3]);
                }
        }
        __syncthreads();
        if (ks + GNST < GNCH)
            gemm_load_stage(sb, s, ks + GNST, m0, n0, tid, A, W);
    }

    int g = lid >> 2, t = lid & 3;
#pragma unroll
    for (int mt = 0; mt < 4; mt++) {
        int mA = m0 + wm * 64 + mt * 16 + g;
        int mB = mA + 8;
        float saA = sa[mA], saB = sa[mB];
#pragma unroll
        for (int nt = 0; nt < 8; nt++) {
            int n = n0 + wn * 64 + (nt >> 1) * 16 + (nt & 1) * 8 + t * 2;
            float2 vsw = *(const float2*)(sw + n);
            float2 vbi = *(const float2*)(bias + n);
            float yA0 = acc[mt][nt][0] * (saA * vsw.x) + vbi.x;
            float yA1 = acc[mt][nt][1] * (saA * vsw.y) + vbi.y;
            float yB0 = acc[mt][nt][2] * (saB * vsw.x) + vbi.x;
            float yB1 = acc[mt][nt][3] * (saB * vsw.y) + vbi.y;
            if (outh) {
                uint32_t hA, lA, hB, lB;
                split2(yA0 * fold, yA1 * fold, hA, lA);
                split2(yB0 * fold, yB1 * fold, hB, lB);
                *(uint32_t*)(outh + (size_t)mA * CC + n) = hA;
                *(uint32_t*)(outl + (size_t)mA * CC + n) = lA;
                *(uint32_t*)(outh + (size_t)mB * CC + n) = hB;
                *(uint32_t*)(outl + (size_t)mB * CC + n) = lB;
            } else {
                *(float2*)(out + (size_t)mA * CC + n) = make_float2(yA0, yA1);
                *(float2*)(out + (size_t)mB * CC + n) = make_float2(yB0, yB1);
            }
        }
    }
}

// -------------------- fp16-split tensor GEMM for K/V projections -----------
#define KVPL 16384u
#define KVSTAGE (4u * KVPL)
#define KV_SMEM (2u * KVSTAGE)
#define KVNCH (CC / 64)

__device__ __forceinline__ void kv_load_stage(
    uint32_t sbase, int s, int ks, int m0, int n0, int tid,
    const __half* __restrict__ Bh, const __half* __restrict__ Bl)
{
    size_t coff = (size_t)ks * 64;
    uint32_t st = sbase + (uint32_t)s * KVSTAGE;
#pragma unroll
    for (int j = 0; j < 16; j++) {
        int gi = tid + j * 256;
        int plane = gi >> 10;
        int within = gi & 1023;
        int r = within >> 3, i = within & 7;
        const __half* arr = (plane == 0) ? g_ch_ : (plane == 1) ? g_cl_
                          : (plane == 2) ? Bh : Bl;
        int row = (plane < 2 ? m0 : n0) + r;
        cp16(st + (uint32_t)plane * KVPL + SW128((uint32_t)(r * 128 + i * 16)),
             arr + (size_t)row * CC + coff + i * 8);
    }
    asm volatile("cp.async.commit_group;" ::: "memory");
}

__global__ __launch_bounds__(256, 1) void gemm_kv_tc(
    const float* __restrict__ bk, const float* __restrict__ bv)
{
    extern __shared__ char smem[];
    uint32_t sb = smem_u32(smem);
    int tid = threadIdx.x;
    int wid = tid >> 5, lid = tid & 31;
    int m0 = blockIdx.y * 128, n0 = blockIdx.x * 128;
    int wm = wid >> 2, wn = wid & 3;
    int z = blockIdx.z;
    const __half* Bh = z ? g_wvh_ : g_wkh_;
    const __half* Bl = z ? g_wvl_ : g_wkl_;
    const float* bias = z ? bv : bk;
    __half* outh = z ? g_vh_ : g_kh_;
    __half* outl = z ? g_vl_ : g_kl_;

    int lrow = (lid & 7) + ((lid >> 3) & 1) * 8;
    int lcol = (lid >> 4) * 16;

    float acc[4][4][4];
#pragma unroll
    for (int mt = 0; mt < 4; mt++)
#pragma unroll
        for (int nt = 0; nt < 4; nt++)
#pragma unroll
            for (int q = 0; q < 4; q++) acc[mt][nt][q] = 0.f;

    kv_load_stage(sb, 0, 0, m0, n0, tid, Bh, Bl);
    kv_load_stage(sb, 1, 1, m0, n0, tid, Bh, Bl);

    int a_row = wm * 64 + lrow;
    int b_row = wn * 32 + lrow;

    for (int ks = 0; ks < KVNCH; ks++) {
        int s = ks & 1;
        if (ks < KVNCH - 1) asm volatile("cp.async.wait_group 1;" ::: "memory");
        else                asm volatile("cp.async.wait_group 0;" ::: "memory");
        __syncthreads();
        uint32_t st = sb + (uint32_t)s * KVSTAGE;
#pragma unroll
        for (int kt = 0; kt < 4; kt++) {
            int kb = kt * 32 + lcol;
            uint32_t ah[4][4], al_[4][4];
#pragma unroll
            for (int mt = 0; mt < 4; mt++) {
                uint32_t ro = SW128((uint32_t)((a_row + mt * 16) * 128 + kb));
                LDSM4(ah[mt][0], ah[mt][1], ah[mt][2], ah[mt][3], st + ro);
                LDSM4(al_[mt][0], al_[mt][1], al_[mt][2], al_[mt][3], st + KVPL + ro);
            }
            uint32_t bh[2][4], bl_[2][4];
#pragma unroll
            for (int np = 0; np < 2; np++) {
                uint32_t ro = SW128((uint32_t)((b_row + np * 16) * 128 + kb));
                LDSM4(bh[np][0], bh[np][1], bh[np][2], bh[np][3], st + 2u * KVPL + ro);
                LDSM4(bl_[np][0], bl_[np][1], bl_[np][2], bl_[np][3], st + 3u * KVPL + ro);
            }
#pragma unroll
            for (int mt = 0; mt < 4; mt++)
#pragma unroll
                for (int np = 0; np < 2; np++) {
                    mma_h(acc[mt][np * 2 + 0], ah[mt],  bh[np][0],  bh[np][2]);
                    mma_h(acc[mt][np * 2 + 0], ah[mt],  bl_[np][0], bl_[np][2]);
                    mma_h(acc[mt][np * 2 + 0], al_[mt], bh[np][0],  bh[np][2]);
                    mma_h(acc[mt][np * 2 + 1], ah[mt],  bh[np][1],  bh[np][3]);
                    mma_h(acc[mt][np * 2 + 1], ah[mt],  bl_[np][1], bl_[np][3]);
                    mma_h(acc[mt][np * 2 + 1], al_[mt], bh[np][1],  bh[np][3]);
                }
        }
        __syncthreads();
        if (ks + 2 < KVNCH)
            kv_load_stage(sb, s, ks + 2, m0, n0, tid, Bh, Bl);
    }

    int g = lid >> 2, t = lid & 3;
#pragma unroll
    for (int mt = 0; mt < 4; mt++) {
        int mA = m0 + wm * 64 + mt * 16 + g;
        int mB = mA + 8;
#pragma unroll
        for (int nt = 0; nt < 4; nt++) {
            int n = n0 + wn * 32 + nt * 8 + t * 2;
            float2 vbi = *(const float2*)(bias + n);
            uint32_t hA, lA, hB, lB;
            split2(acc[mt][nt][0] + vbi.x, acc[mt][nt][1] + vbi.y, hA, lA);
            split2(acc[mt][nt][2] + vbi.x, acc[mt][nt][3] + vbi.y, hB, lB);
            *(uint32_t*)(outh + (size_t)mA * CC + n) = hA;
            *(uint32_t*)(outl + (size_t)mA * CC + n) = lA;
            *(uint32_t*)(outh + (size_t)mB * CC + n) = hB;
            *(uint32_t*)(outl + (size_t)mB * CC + n) = lB;
        }
    }
}

// -------------------- fp16-split tensor-core flash attention ---------------
#define ATT_SMEM (192*1024)

__device__ __forceinline__ void attn_load_kv(uint32_t base, int chunk,
                                             int b, int h, int tid) {
    size_t rowbase = (size_t)b * LL + chunk * 64;
#pragma unroll
    for (int j = 0; j < 16; j++) {
        int gi = tid + j * 256;
        int plane = gi >> 9;
        int within = gi & 511;
        int r = within >> 3, i = within & 7;
        const __half* arr = (plane < 2) ? g_kh_ : (plane < 4) ? g_kl_
                          : (plane < 6) ? g_vh_ : g_vl_;
        cp16(base + (uint32_t)plane * 8192u + SW128((uint32_t)(r * 128 + i * 16)),
             arr + (rowbase + r) * CC + h * DD + (plane & 1) * 64 + i * 8);
    }
    asm volatile("cp.async.commit_group;" ::: "memory");
}

__global__ __launch_bounds__(256, 1) void attn_tc(const float* __restrict__ mask)
{
    extern __shared__ char smem[];
    uint32_t sb = smem_u32(smem);
    int tid = threadIdx.x;
    int wid = tid >> 5, lid = tid & 31;
    int b = blockIdx.y >> 4, h = blockIdx.y & 15;
    int n0 = blockIdx.x * 128;
    int lrow = (lid & 7) + ((lid >> 3) & 1) * 8;
    int lcol = (lid >> 4) * 16;
    int g = lid >> 2, t = lid & 3;

    {
        size_t rowbase = (size_t)b * NN + n0;
#pragma unroll
        for (int j = 0; j < 16; j++) {
            int gi = tid + j * 256;
            int plane = gi >> 10;
            int within = gi & 1023;
            int r = within >> 3, i = within & 7;
            const __half* arr = (plane < 2) ? g_qh_ : g_ql_;
            cp16(sb + (uint32_t)plane * 16384u + SW128((uint32_t)(r * 128 + i * 16)),
                 arr + (rowbase + r) * CC + h * DD + (plane & 1) * 64 + i * 8);
        }
        asm volatile("cp.async.commit_group;" ::: "memory");
    }
    attn_load_kv(sb + 65536u, 0, b, h, tid);

    asm volatile("cp.async.wait_group 1;" ::: "memory");
    __syncthreads();
    uint32_t qh_f[8][4], ql_f[8][4];
#pragma unroll
    for (int kt = 0; kt < 8; kt++) {
        uint32_t ro = SW128((uint32_t)((wid * 16 + lrow) * 128 + (kt & 3) * 32 + lcol));
        uint32_t ph = (uint32_t)(kt >> 2) * 16384u;
        LDSM4(qh_f[kt][0], qh_f[kt][1], qh_f[kt][2], qh_f[kt][3], sb + ph + ro);
        LDSM4(ql_f[kt][0], ql_f[kt][1], ql_f[kt][2], ql_f[kt][3], sb + 32768u + ph + ro);
    }
    __syncthreads();
    attn_load_kv(sb, 1, b, h, tid);

    float m0r = -INFINITY, m1r = -INFINITY, l0r = 0.f, l1r = 0.f;
    float oacc[16][4];
#pragma unroll
    for (int j = 0; j < 16; j++)
#pragma unroll
        for (int q = 0; q < 4; q++) oacc[j][q] = 0.f;

    const float* mr0 = mask + ((size_t)b * NN + n0 + wid * 16 + g) * LL + 2 * t;
    const float* mr1 = mr0 + 8 * LL;

    for (int c = 0; c < LL / 64; c++) {
        uint32_t kvb = (c & 1) ? sb : (sb + 65536u);
        if (c < LL / 64 - 1) asm volatile("cp.async.wait_group 1;" ::: "memory");
        else                 asm volatile("cp.async.wait_group 0;" ::: "memory");
        __syncthreads();

        float sacc[8][4];
#pragma unroll
        for (int j = 0; j < 8; j++) {
            float2 a = *(const float2*)(mr0 + c * 64 + j * 8);
            float2 d = *(const float2*)(mr1 + c * 64 + j * 8);
            sacc[j][0] = a.x * L2E; sacc[j][1] = a.y * L2E;
            sacc[j][2] = d.x * L2E; sacc[j][3] = d.y * L2E;
        }
#pragma unroll
        for (int kt = 0; kt < 8; kt++) {
            uint32_t pk = (uint32_t)(kt >> 2) * 8192u;
            uint32_t kb = (uint32_t)((kt & 3) * 32 + lcol);
#pragma unroll
            for (int j16 = 0; j16 < 4; j16++) {
                uint32_t ro = SW128((uint32_t)((j16 * 16 + lrow) * 128) + kb);
                uint32_t kh0, kh1, kh2, kh3, kl0, kl1, kl2, kl3;
                LDSM4(kh0, kh1, kh2, kh3, kvb + pk + ro);
                LDSM4(kl0, kl1, kl2, kl3, kvb + 16384u + pk + ro);
                mma_h(sacc[2 * j16],     qh_f[kt], kh0, kh2);
                mma_h(sacc[2 * j16],     qh_f[kt], kl0, kl2);
                mma_h(sacc[2 * j16],     ql_f[kt], kh0, kh2);
                mma_h(sacc[2 * j16 + 1], qh_f[kt], kh1, kh3);
                mma_h(sacc[2 * j16 + 1], qh_f[kt], kl1, kl3);
                mma_h(sacc[2 * j16 + 1], ql_f[kt], kh1, kh3);
            }
        }

        float mx0 = -INFINITY, mx1 = -INFINITY;
#pragma unroll
        for (int j = 0; j < 8; j++) {
            mx0 = fmaxf(mx0, fmaxf(sacc[j][0], sacc[j][1]));
            mx1 = fmaxf(mx1, fmaxf(sacc[j][2], sacc[j][3]));
        }
#pragma unroll
        for (int off = 1; off < 4; off <<= 1) {
            mx0 = fmaxf(mx0, __shfl_xor_sync(0xffffffffu, mx0, off));
            mx1 = fmaxf(mx1, __shfl_xor_sync(0xffffffffu, mx1, off));
        }
        float nm0 = fmaxf(m0r, mx0), nm1 = fmaxf(m1r, mx1);
        float cr0 = exp2_poly(m0r - nm0), cr1 = exp2_poly(m1r - nm1);
        m0r = nm0; m1r = nm1;

        uint32_t pa_h[4][4], pa_l[4][4];
        float rs0 = 0.f, rs1 = 0.f;
#pragma unroll
        for (int j = 0; j < 8; j++) {
            float p0 = exp2_poly(sacc[j][0] - nm0);
            float p1 = exp2_poly(sacc[j][1] - nm0);
            float p2 = exp2_poly(sacc[j][2] - nm1);
            float p3 = exp2_poly(sacc[j][3] - nm1);
            rs0 += p0 + p1; rs1 += p2 + p3;
            uint32_t h01 = packh(p0, p1), h23 = packh(p2, p3);
            __half2 hh01 = *(__half2*)&h01, hh23 = *(__half2*)&h23;
            uint32_t l01 = packh(p0 - __low2float(hh01),  p1 - __high2float(hh01));
            uint32_t l23 = packh(p2 - __low2float(hh23),  p3 - __high2float(hh23));
            int kt2 = j >> 1, sl = (j & 1) * 2;
            pa_h[kt2][sl] = h01; pa_h[kt2][sl + 1] = h23;
            pa_l[kt2][sl] = l01; pa_l[kt2][sl + 1] = l23;
        }
#pragma unroll
        for (int off = 1; off < 4; off <<= 1) {
            rs0 += __shfl_xor_sync(0xffffffffu, rs0, off);
            rs1 += __shfl_xor_sync(0xffffffffu, rs1, off);
        }
        l0r = l0r * cr0 + rs0;
        l1r = l1r * cr1 + rs1;
#pragma unroll
        for (int j = 0; j < 16; j++) {
            oacc[j][0] *= cr0; oacc[j][1] *= cr0;
            oacc[j][2] *= cr1; oacc[j][3] *= cr1;
        }

#pragma unroll
        for (int lt = 0; lt < 4; lt++) {
#pragma unroll
            for (int dq = 0; dq < 8; dq++) {
                uint32_t pv = (uint32_t)(4 + (dq >> 2)) * 8192u;
                uint32_t ro = SW128((uint32_t)((lt * 16 + lrow) * 128 + (dq & 3) * 32 + lcol));
                uint32_t vh0, vh1, vh2, vh3, vl0, vl1, vl2, vl3;
                LDSM4T(vh0, vh1, vh2, vh3, kvb + pv + ro);
                LDSM4T(vl0, vl1, vl2, vl3, kvb + 16384u + pv + ro);
                mma_h(oacc[2 * dq],     pa_h[lt], vh0, vh1);
                mma_h(oacc[2 * dq],     pa_h[lt], vl0, vl1);
                mma_h(oacc[2 * dq],     pa_l[lt], vh0, vh1);
                mma_h(oacc[2 * dq + 1], pa_h[lt], vh2, vh3);
                mma_h(oacc[2 * dq + 1], pa_h[lt], vl2, vl3);
                mma_h(oacc[2 * dq + 1], pa_l[lt], vh2, vh3);
            }
        }
        __syncthreads();
        if (c + 2 < LL / 64)
            attn_load_kv(kvb, c + 2, b, h, tid);
    }

    float inv0 = 1.f / l0r, inv1 = 1.f / l1r;
    float* o0 = g_o + ((size_t)b * NN + n0 + wid * 16 + g) * CC + h * DD + 2 * t;
    float* o1 = o0 + 8 * (size_t)CC;
#pragma unroll
    for (int dn = 0; dn < 16; dn++) {
        *(float2*)(o0 + dn * 8) = make_float2(oacc[dn][0] * inv0, oacc[dn][1] * inv0);
        *(float2*)(o1 + dn * 8) = make_float2(oacc[dn][2] * inv1, oacc[dn][3] * inv1);
    }
}

// -------------------- launcher (forked-graph schedule) ---------------------
extern "C" void kernel_launch(void* const* d_in, const int* in_sizes, int n_in,
                              void* d_out, int out_size) {
    const float* x    = (const float*)d_in[0];
    const float* cond = (const float*)d_in[1];
    const float* mask = (const float*)d_in[2];
    const float* wq   = (const float*)d_in[3];
    const float* bq   = (const float*)d_in[4];
    const float* wk   = (const float*)d_in[5];
    const float* bk   = (const float*)d_in[6];
    const float* wv   = (const float*)d_in[7];
    const float* bv   = (const float*)d_in[8];
    const float* wo   = (const float*)d_in[9];
    const float* bo   = (const float*)d_in[10];
    float* out = (float*)d_out;

    void *p_qwq, *p_swq, *p_qwo, *p_swo, *p_qx, *p_sx, *p_o, *p_qo, *p_so;
    void *p_qh, *p_ql, *p_ch, *p_cl, *p_wkh, *p_wkl, *p_wvh, *p_wvl;
    cudaGetSymbolAddress(&p_qwq, g_qwq);
    cudaGetSymbolAddress(&p_swq, g_swq);
    cudaGetSymbolAddress(&p_qwo, g_qwo);
    cudaGetSymbolAddress(&p_swo, g_swo);
    cudaGetSymbolAddress(&p_qx,  g_qx);
    cudaGetSymbolAddress(&p_sx,  g_sx);
    cudaGetSymbolAddress(&p_o,   g_o);
    cudaGetSymbolAddress(&p_qo,  g_qo);
    cudaGetSymbolAddress(&p_so,  g_so);
    cudaGetSymbolAddress(&p_qh,  g_qh_);
    cudaGetSymbolAddress(&p_ql,  g_ql_);
    cudaGetSymbolAddress(&p_ch,  g_ch_);
    cudaGetSymbolAddress(&p_cl,  g_cl_);
    cudaGetSymbolAddress(&p_wkh, g_wkh_);
    cudaGetSymbolAddress(&p_wkl, g_wkl_);
    cudaGetSymbolAddress(&p_wvh, g_wvh_);
    cudaGetSymbolAddress(&p_wvl, g_wvl_);

    cudaFuncSetAttribute(gemm_tc,
                         cudaFuncAttributeMaxDynamicSharedMemorySize, GEMM_SMEM);
    cudaFuncSetAttribute(gemm_kv_tc,
                         cudaFuncAttributeMaxDynamicSharedMemorySize, KV_SMEM);
    cudaFuncSetAttribute(attn_tc,
                         cudaFuncAttributeMaxDynamicSharedMemorySize, ATT_SMEM);

    // One-time side-stream + fork/join events (host-side infra; launched work
    // is identical on every call, as the harness requires).
    static cudaStream_t s1 = nullptr;
    static cudaEvent_t eFork = nullptr, eJoin = nullptr;
    if (!s1) {
        cudaStreamCreateWithFlags(&s1, cudaStreamNonBlocking);
        cudaEventCreateWithFlags(&eFork, cudaEventDisableTiming);
        cudaEventCreateWithFlags(&eJoin, cudaEventDisableTiming);
    }

    // ---- fork: branch B (KV pipeline + wo quant) runs on s1 ----
    cudaEventRecord(eFork, 0);
    cudaStreamWaitEvent(s1, eFork, 0);

    // Branch B (s1): cond/wk/wv splits -> KV projections; wo quant for Oproj
    split_f32<<<(MKV * CC) / 256, 256, 0, s1>>>(cond, (__half*)p_ch, (__half*)p_cl, MKV * CC);
    split_f32<<<(CC * CC) / 256, 256, 0, s1>>>(wk, (__half*)p_wkh, (__half*)p_wkl, CC * CC);
    split_f32<<<(CC * CC) / 256, 256, 0, s1>>>(wv, (__half*)p_wvh, (__half*)p_wvl, CC * CC);
    gemm_kv_tc<<<dim3(CC / 128, MKV / 128, 2), 256, KV_SMEM, s1>>>(bk, bv);
    quant_rows<<<CC, 256, 0, s1>>>(wo, (__nv_bfloat16*)p_qwo, (float*)p_swo);
    cudaEventRecord(eJoin, s1);

    // Branch A (stream 0): x/wq quant -> Q projection
    quant_rows<<<CC, 256>>>(wq, (__nv_bfloat16*)p_qwq, (float*)p_swq);
    quant_rows<<<MTOK, 256>>>(x, (__nv_bfloat16*)p_qx, (float*)p_sx);
    gemm_tc<<<dim3(CC / 256, MTOK / 128), 256, GEMM_SMEM>>>(
        (const __nv_bfloat16*)p_qx, (const __nv_bfloat16*)p_qwq,
        (const float*)p_sx, (const float*)p_swq, bq, nullptr,
        (__half*)p_qh, (__half*)p_ql, QFOLD);

    // ---- join: attention needs Q (branch A) and K/V (branch B) ----
    cudaStreamWaitEvent(0, eJoin, 0);

    attn_tc<<<dim3(NN / 128, BB * HH), 256, ATT_SMEM>>>(mask);

    quant_rows<<<MTOK, 256>>>((const float*)p_o, (__nv_bfloat16*)p_qo, (float*)p_so);
    gemm_tc<<<dim3(CC / 256, MTOK / 128), 256, GEMM_SMEM>>>(
        (const __nv_bfloat16*)p_qo, (const __nv_bfloat16*)p_qwo,
        (const float*)p_so, (const float*)p_swo, bo, out,
        nullptr, nullptr, 1.0f);
}